// round 1
// baseline (speedup 1.0000x reference)
#include <cuda_runtime.h>
#include <cstdint>

#define NN 50000
#define EE 800000
#define FF 128
#define KK 8
#define DD 16
#define GG 512
#define GC 3
#define BN_EPS 1e-5f

// ---------------- static scratch (no allocations allowed) ----------------
__device__ float d_h[NN * FF];     // current node features
__device__ float d_agg[NN * FF];   // aggregation target (pre-seeded with h) -> z
__device__ float d_t[NN * FF];     // relu intermediate
__device__ float d_z[NN * FF];     // post-MLP, pre-BN
__device__ float d_bsum[FF];
__device__ float d_bsq[FF];
__device__ float d_scale[FF];
__device__ float d_shift[FF];
__device__ float d_Wcat[FF * FF];
__device__ float d_bcat[FF];

// ---------------- init: h = agg = x ----------------
__global__ void __launch_bounds__(256) copy2_kernel(const float* __restrict__ x) {
    int idx = blockIdx.x * 256 + threadIdx.x;          // float4 index over N*F/4
    if (idx >= NN * 32) return;
    float4 v = ((const float4*)x)[idx];
    ((float4*)d_h)[idx] = v;
    ((float4*)d_agg)[idx] = v;
}

// ---------------- scatter: agg[dst] += h[src], warp per edge ----------------
__global__ void __launch_bounds__(256) scatter_kernel(const int* __restrict__ src,
                                                      const int* __restrict__ dst) {
    int gt = blockIdx.x * 256 + threadIdx.x;
    int e = gt >> 5;
    int lane = gt & 31;
    if (e >= EE) return;
    int s = src[e];
    int d = dst[e];
    float4 v = ((const float4*)(d_h + (size_t)s * FF))[lane];
    float* out = d_agg + (size_t)d * FF + lane * 4;
    asm volatile("red.global.add.v4.f32 [%0], {%1,%2,%3,%4};"
                 :: "l"(out), "f"(v.x), "f"(v.y), "f"(v.z), "f"(v.w) : "memory");
}

// ---------------- SGEMM: C[M,128] = relu?(A[M,128] @ W[128,128] + b) ----------------
__global__ void __launch_bounds__(256) gemm128_kernel(const float* __restrict__ A,
                                                      const float* __restrict__ W,
                                                      const float* __restrict__ bias,
                                                      float* __restrict__ C,
                                                      int M, int relu) {
    __shared__ float As[16][128];   // [k][m]
    __shared__ float Bs[16][128];   // [k][n]
    const int tid = threadIdx.x;
    const int row0 = blockIdx.x * 128;
    const int trow = (tid >> 4) << 3;   // 0..120 step 8
    const int tcol = (tid & 15) << 3;   // 0..120 step 8

    float acc[8][8];
#pragma unroll
    for (int i = 0; i < 8; i++)
#pragma unroll
        for (int j = 0; j < 8; j++) acc[i][j] = 0.f;

    const int ar = tid >> 2;           // A: row within tile (0..63), +64 for 2nd
    const int ac = (tid & 3) << 2;     // A: k offset (float4)
    const int br = tid >> 5;           // B: k row (0..7), +8 for 2nd
    const int bc = (tid & 31) << 2;    // B: n offset (float4)

    for (int k0 = 0; k0 < 128; k0 += 16) {
        int r1 = row0 + ar;      if (r1 >= M) r1 = M - 1;
        int r2 = row0 + ar + 64; if (r2 >= M) r2 = M - 1;
        float4 a1 = *(const float4*)(A + (size_t)r1 * 128 + k0 + ac);
        float4 a2 = *(const float4*)(A + (size_t)r2 * 128 + k0 + ac);
        As[ac + 0][ar] = a1.x; As[ac + 1][ar] = a1.y;
        As[ac + 2][ar] = a1.z; As[ac + 3][ar] = a1.w;
        As[ac + 0][ar + 64] = a2.x; As[ac + 1][ar + 64] = a2.y;
        As[ac + 2][ar + 64] = a2.z; As[ac + 3][ar + 64] = a2.w;
        float4 b1 = *(const float4*)(W + (size_t)(k0 + br) * 128 + bc);
        float4 b2 = *(const float4*)(W + (size_t)(k0 + br + 8) * 128 + bc);
        *(float4*)&Bs[br][bc] = b1;
        *(float4*)&Bs[br + 8][bc] = b2;
        __syncthreads();
#pragma unroll
        for (int kk = 0; kk < 16; kk++) {
            float4 ra0 = *(const float4*)&As[kk][trow];
            float4 ra1 = *(const float4*)&As[kk][trow + 4];
            float4 rb0 = *(const float4*)&Bs[kk][tcol];
            float4 rb1 = *(const float4*)&Bs[kk][tcol + 4];
            float ra[8] = {ra0.x, ra0.y, ra0.z, ra0.w, ra1.x, ra1.y, ra1.z, ra1.w};
            float rb[8] = {rb0.x, rb0.y, rb0.z, rb0.w, rb1.x, rb1.y, rb1.z, rb1.w};
#pragma unroll
            for (int i = 0; i < 8; i++)
#pragma unroll
                for (int j = 0; j < 8; j++) acc[i][j] += ra[i] * rb[j];
        }
        __syncthreads();
    }

    float4 bv0 = *(const float4*)(bias + tcol);
    float4 bv1 = *(const float4*)(bias + tcol + 4);
    float bvals[8] = {bv0.x, bv0.y, bv0.z, bv0.w, bv1.x, bv1.y, bv1.z, bv1.w};
#pragma unroll
    for (int i = 0; i < 8; i++) {
        int r = row0 + trow + i;
        if (r < M) {
            float o[8];
#pragma unroll
            for (int j = 0; j < 8; j++) {
                float v = acc[i][j] + bvals[j];
                o[j] = relu ? fmaxf(v, 0.f) : v;
            }
            *(float4*)(C + (size_t)r * 128 + tcol)     = make_float4(o[0], o[1], o[2], o[3]);
            *(float4*)(C + (size_t)r * 128 + tcol + 4) = make_float4(o[4], o[5], o[6], o[7]);
        }
    }
}

// ---------------- BN stats ----------------
__global__ void __launch_bounds__(128) bn_stats_kernel(const float* __restrict__ z) {
    int f = threadIdx.x;
    int per = (NN + gridDim.x - 1) / gridDim.x;
    int n0 = blockIdx.x * per;
    int n1 = n0 + per; if (n1 > NN) n1 = NN;
    float s = 0.f, q = 0.f;
    for (int n = n0; n < n1; n++) {
        float v = z[(size_t)n * FF + f];
        s += v; q += v * v;
    }
    atomicAdd(&d_bsum[f], s);
    atomicAdd(&d_bsq[f], q);
}

__global__ void bn_fin_kernel(const float* __restrict__ g, const float* __restrict__ be) {
    int f = threadIdx.x;  // 128 threads
    float mu  = d_bsum[f] * (1.0f / NN);
    float var = d_bsq[f]  * (1.0f / NN) - mu * mu;
    float sc = g[f] * rsqrtf(var + BN_EPS);
    d_scale[f] = sc;
    d_shift[f] = be[f] - mu * sc;
    d_bsum[f] = 0.f;   // self-reset for graph replay
    d_bsq[f]  = 0.f;
}

// ---------------- BN apply (+relu) -> h (and agg if dup) ----------------
__global__ void __launch_bounds__(256) apply_kernel(const float* __restrict__ z,
                                                    int relu, int dup) {
    int idx = blockIdx.x * 256 + threadIdx.x;
    if (idx >= NN * 32) return;
    int f4 = (idx & 31) << 2;
    float4 v = ((const float4*)z)[idx];
    float4 sc = *(const float4*)&d_scale[f4];
    float4 sh = *(const float4*)&d_shift[f4];
    v.x = v.x * sc.x + sh.x; v.y = v.y * sc.y + sh.y;
    v.z = v.z * sc.z + sh.z; v.w = v.w * sc.w + sh.w;
    if (relu) {
        v.x = fmaxf(v.x, 0.f); v.y = fmaxf(v.y, 0.f);
        v.z = fmaxf(v.z, 0.f); v.w = fmaxf(v.w, 0.f);
    }
    ((float4*)d_h)[idx] = v;
    if (dup) ((float4*)d_agg)[idx] = v;
}

// ---------------- concat head0 W1/b1: Wcat[i,k*16+j] = h0_W1[k,i,j] ----------------
__global__ void prep_cat_kernel(const float* __restrict__ W1, const float* __restrict__ b1) {
    int idx = blockIdx.x * 256 + threadIdx.x;
    if (idx < FF * FF) {
        int i = idx >> 7, c = idx & 127;
        int k = c >> 4, j = c & 15;
        d_Wcat[idx] = W1[k * (FF * DD) + i * DD + j];
    }
    if (idx < FF) {
        int k = idx >> 4, j = idx & 15;
        d_bcat[idx] = b1[k * DD + j];
    }
}

// ---------------- block-diag 16x16 GEMM (single): C_k = X_k @ W_k + b_k ----------------
__global__ void __launch_bounds__(256) bdiag1_kernel(const float* __restrict__ X,
                                                     const float* __restrict__ W,
                                                     const float* __restrict__ B,
                                                     float* __restrict__ C) {
    __shared__ float sW[8 * 257];   // pad 257 -> per-k bank offset
    __shared__ float sB[128];
    int tid = threadIdx.x;
    for (int i = tid; i < 2048; i += 256) sW[(i >> 8) * 257 + (i & 255)] = W[i];
    if (tid < 128) sB[tid] = B[tid];
    __syncthreads();
    int k = tid & 7;
    int n = blockIdx.x * 32 + (tid >> 3);
    if (n >= NN) return;
    const float4* xp = (const float4*)(X + (size_t)n * FF + k * DD);
    float x[16];
#pragma unroll
    for (int i = 0; i < 4; i++) {
        float4 v = xp[i];
        x[4*i] = v.x; x[4*i+1] = v.y; x[4*i+2] = v.z; x[4*i+3] = v.w;
    }
    const float* wk = sW + k * 257;
    float o[16];
#pragma unroll
    for (int j = 0; j < 16; j++) o[j] = sB[k * 16 + j];
#pragma unroll
    for (int i = 0; i < 16; i++) {
        float xi = x[i];
#pragma unroll
        for (int j = 0; j < 16; j++) o[j] += xi * wk[i * 16 + j];
    }
    float4* cp = (float4*)(C + (size_t)n * FF + k * DD);
#pragma unroll
    for (int i = 0; i < 4; i++)
        cp[i] = make_float4(o[4*i], o[4*i+1], o[4*i+2], o[4*i+3]);
}

// ---------------- block-diag double: C_k = relu(X_k@W1_k+b1_k)@W2_k+b2_k ----------------
__global__ void __launch_bounds__(256) bdiag2_kernel(const float* __restrict__ X,
                                                     const float* __restrict__ W1,
                                                     const float* __restrict__ B1,
                                                     const float* __restrict__ W2,
                                                     const float* __restrict__ B2,
                                                     float* __restrict__ C) {
    __shared__ float sW1[8 * 257];
    __shared__ float sW2[8 * 257];
    __shared__ float sB1[128];
    __shared__ float sB2[128];
    int tid = threadIdx.x;
    for (int i = tid; i < 2048; i += 256) {
        sW1[(i >> 8) * 257 + (i & 255)] = W1[i];
        sW2[(i >> 8) * 257 + (i & 255)] = W2[i];
    }
    if (tid < 128) { sB1[tid] = B1[tid]; sB2[tid] = B2[tid]; }
    __syncthreads();
    int k = tid & 7;
    int n = blockIdx.x * 32 + (tid >> 3);
    if (n >= NN) return;
    const float4* xp = (const float4*)(X + (size_t)n * FF + k * DD);
    float x[16];
#pragma unroll
    for (int i = 0; i < 4; i++) {
        float4 v = xp[i];
        x[4*i] = v.x; x[4*i+1] = v.y; x[4*i+2] = v.z; x[4*i+3] = v.w;
    }
    const float* w1 = sW1 + k * 257;
    const float* w2 = sW2 + k * 257;
    float t[16];
#pragma unroll
    for (int j = 0; j < 16; j++) t[j] = sB1[k * 16 + j];
#pragma unroll
    for (int i = 0; i < 16; i++) {
        float xi = x[i];
#pragma unroll
        for (int j = 0; j < 16; j++) t[j] += xi * w1[i * 16 + j];
    }
#pragma unroll
    for (int j = 0; j < 16; j++) t[j] = fmaxf(t[j], 0.f);
    float o[16];
#pragma unroll
    for (int j = 0; j < 16; j++) o[j] = sB2[k * 16 + j];
#pragma unroll
    for (int i = 0; i < 16; i++) {
        float ti = t[i];
#pragma unroll
        for (int j = 0; j < 16; j++) o[j] += ti * w2[i * 16 + j];
    }
    float4* cp = (float4*)(C + (size_t)n * FF + k * DD);
#pragma unroll
    for (int i = 0; i < 4; i++)
        cp[i] = make_float4(o[4*i], o[4*i+1], o[4*i+2], o[4*i+3]);
}

// ---------------- pooling ----------------
__global__ void zero_out_kernel(float* __restrict__ out) {
    int idx = blockIdx.x * 256 + threadIdx.x;
    if (idx < GG * FF) out[idx] = 0.f;
}

__global__ void __launch_bounds__(256) pool_kernel(const int* __restrict__ batch,
                                                   float* __restrict__ out) {
    int idx = blockIdx.x * 256 + threadIdx.x;
    if (idx >= NN * 32) return;
    int n = idx >> 5;
    int f4 = idx & 31;
    int g = batch[n];
    float4 v = ((const float4*)d_h)[idx];
    float* op = out + (size_t)g * FF + f4 * 4;
    asm volatile("red.global.add.v4.f32 [%0], {%1,%2,%3,%4};"
                 :: "l"(op), "f"(v.x), "f"(v.y), "f"(v.z), "f"(v.w) : "memory");
}

// ---------------- host orchestration ----------------
extern "C" void kernel_launch(void* const* d_in, const int* in_sizes, int n_in,
                              void* d_out, int out_size) {
    const float* x     = (const float*)d_in[0];
    const int*   ei    = (const int*)d_in[1];
    const int*   batch = (const int*)d_in[2];
    // d_in[3] = num_graphs (unused, compile-time G)
    const float* gc_W1 = (const float*)d_in[4];
    const float* gc_b1 = (const float*)d_in[5];
    const float* gc_W2 = (const float*)d_in[6];
    const float* gc_b2 = (const float*)d_in[7];
    const float* gc_g  = (const float*)d_in[8];
    const float* gc_be = (const float*)d_in[9];
    const float* h0_W1 = (const float*)d_in[10];
    const float* h0_b1 = (const float*)d_in[11];
    const float* h0_W2 = (const float*)d_in[12];
    const float* h0_b2 = (const float*)d_in[13];
    const float* h0_g  = (const float*)d_in[14];
    const float* h0_be = (const float*)d_in[15];
    const float* h1_W1 = (const float*)d_in[16];
    const float* h1_b1 = (const float*)d_in[17];
    const float* h1_W2 = (const float*)d_in[18];
    const float* h1_b2 = (const float*)d_in[19];
    const float* h1_g  = (const float*)d_in[20];
    const float* h1_be = (const float*)d_in[21];
    float* out = (float*)d_out;

    const int* src = ei;
    const int* dst = ei + EE;

    float *ph, *pagg, *pt, *pz, *pWcat, *pbcat;
    cudaGetSymbolAddress((void**)&ph, d_h);
    cudaGetSymbolAddress((void**)&pagg, d_agg);
    cudaGetSymbolAddress((void**)&pt, d_t);
    cudaGetSymbolAddress((void**)&pz, d_z);
    cudaGetSymbolAddress((void**)&pWcat, d_Wcat);
    cudaGetSymbolAddress((void**)&pbcat, d_bcat);

    const int grid_nf   = (NN * 32 + 255) / 256;       // 6250
    const int grid_scat = (EE * 32) / 256;             // 100000
    const int grid_gemm = (NN + 127) / 128;            // 391
    const int grid_bd   = (NN + 31) / 32;              // 1563

    copy2_kernel<<<grid_nf, 256>>>(x);

    for (int i = 0; i < GC; i++) {
        scatter_kernel<<<grid_scat, 256>>>(src, dst);
        gemm128_kernel<<<grid_gemm, 256>>>(pagg, gc_W1 + i * FF * FF, gc_b1 + i * FF, pt, NN, 1);
        gemm128_kernel<<<grid_gemm, 256>>>(pt,   gc_W2 + i * FF * FF, gc_b2 + i * FF, pz, NN, 0);
        bn_stats_kernel<<<416, 128>>>(pz);
        bn_fin_kernel<<<1, 128>>>(gc_g + i * FF, gc_be + i * FF);
        apply_kernel<<<grid_nf, 256>>>(pz, (i < GC - 1) ? 1 : 0, 1);
    }

    // head layer 0
    scatter_kernel<<<grid_scat, 256>>>(src, dst);
    prep_cat_kernel<<<64, 256>>>(h0_W1, h0_b1);
    gemm128_kernel<<<grid_gemm, 256>>>(pagg, pWcat, pbcat, pt, NN, 1);
    bdiag1_kernel<<<grid_bd, 256>>>(pt, h0_W2, h0_b2, pz);
    bn_stats_kernel<<<416, 128>>>(pz);
    bn_fin_kernel<<<1, 128>>>(h0_g, h0_be);
    apply_kernel<<<grid_nf, 256>>>(pz, 1, 1);

    // head layer 1
    scatter_kernel<<<grid_scat, 256>>>(src, dst);
    bdiag2_kernel<<<grid_bd, 256>>>(pagg, h1_W1, h1_b1, h1_W2, h1_b2, pz);
    bn_stats_kernel<<<416, 128>>>(pz);
    bn_fin_kernel<<<1, 128>>>(h1_g, h1_be);
    apply_kernel<<<grid_nf, 256>>>(pz, 0, 0);

    // pooling
    zero_out_kernel<<<(GG * FF + 255) / 256, 256>>>(out);
    pool_kernel<<<grid_nf, 256>>>(batch, out);
}

// round 3
// speedup vs baseline: 1.5405x; 1.5405x over previous
#include <cuda_runtime.h>
#include <cstdint>

#define NN 50000
#define EE 800000
#define FF 128
#define KK 8
#define DD 16
#define GG 512
#define GC 3
#define BN_EPS 1e-5f
#define NB 196   // ceil(NN/256)

// ---------------- static scratch ----------------
__device__ float d_agg[NN * FF];
__device__ float d_t[NN * FF];
__device__ float d_z[NN * FF];
__device__ int   d_deg[NN];
__device__ int   d_rowptr[NN];
__device__ int   d_cur[NN];
__device__ int   d_esrc[EE];
__device__ int   d_bsumblk[256];
__device__ float d_bsum[FF];
__device__ float d_bsq[FF];
__device__ float d_scale[FF];
__device__ float d_shift[FF];
__device__ float d_Wcat[FF * FF];
__device__ float d_bcat[FF];

// ================= helpers =================
__device__ __forceinline__ uint32_t smem_u32(const void* p) {
    uint32_t a;
    asm("{ .reg .u64 t; cvta.to.shared.u64 t, %1; cvt.u32.u64 %0, t; }" : "=r"(a) : "l"(p));
    return a;
}

// split fp32 -> bf16 hi + bf16 lo (round-to-nearest-even-ish via +0x7FFF+lsb)
__device__ __forceinline__ void split1(float v, uint32_t& h, uint32_t& l) {
    uint32_t u = __float_as_uint(v);
    uint32_t hr = (u + 0x7FFFu + ((u >> 16) & 1u)) & 0xFFFF0000u;
    float hf = __uint_as_float(hr);
    float lf = v - hf;
    uint32_t ul = __float_as_uint(lf);
    h = hr >> 16;
    l = (ul + 0x7FFFu + ((ul >> 16) & 1u)) >> 16;
}

__device__ __forceinline__ void ldsm4(uint32_t* r, uint32_t addr) {
    asm volatile("ldmatrix.sync.aligned.m8n8.x4.shared.b16 {%0,%1,%2,%3}, [%4];"
                 : "=r"(r[0]), "=r"(r[1]), "=r"(r[2]), "=r"(r[3]) : "r"(addr));
}
__device__ __forceinline__ void ldsm4t(uint32_t* r, uint32_t addr) {
    asm volatile("ldmatrix.sync.aligned.m8n8.x4.trans.shared.b16 {%0,%1,%2,%3}, [%4];"
                 : "=r"(r[0]), "=r"(r[1]), "=r"(r[2]), "=r"(r[3]) : "r"(addr));
}
__device__ __forceinline__ void mma_bf16(float* c, const uint32_t* a, const uint32_t* b) {
    asm volatile(
        "mma.sync.aligned.m16n8k16.row.col.f32.bf16.bf16.f32 "
        "{%0,%1,%2,%3}, {%4,%5,%6,%7}, {%8,%9}, {%0,%1,%2,%3};"
        : "+f"(c[0]), "+f"(c[1]), "+f"(c[2]), "+f"(c[3])
        : "r"(a[0]), "r"(a[1]), "r"(a[2]), "r"(a[3]), "r"(b[0]), "r"(b[1]));
}

// smem: padded rows of 136 bf16 = 272B (17x16B -> ldmatrix conflict-free)
#define RSTRIDE 272
#define O_AH 0
#define O_AL 34816
#define O_WH 69632
#define O_WL 104448
#define SM_TOTAL 139264

// ---------------- CSR build ----------------
__global__ void zero_deg_kernel() {
    int n = blockIdx.x * 256 + threadIdx.x;
    if (n < NN) d_deg[n] = 0;
}
__global__ void hist_kernel(const int* __restrict__ dst) {
    int e = blockIdx.x * 256 + threadIdx.x;
    if (e < EE) atomicAdd(&d_deg[dst[e]], 1);
}
__global__ void scan1_kernel() {
    __shared__ int s[256];
    int n = blockIdx.x * 256 + threadIdx.x;
    s[threadIdx.x] = (n < NN) ? d_deg[n] : 0;
    __syncthreads();
    for (int o = 128; o > 0; o >>= 1) {
        if (threadIdx.x < o) s[threadIdx.x] += s[threadIdx.x + o];
        __syncthreads();
    }
    if (threadIdx.x == 0) d_bsumblk[blockIdx.x] = s[0];
}
__global__ void scan2_kernel() {
    __shared__ int s[256];
    int tid = threadIdx.x;
    int v = (tid < NB) ? d_bsumblk[tid] : 0;
    s[tid] = v;
    __syncthreads();
    for (int o = 1; o < 256; o <<= 1) {
        int t = (tid >= o) ? s[tid - o] : 0;
        __syncthreads();
        s[tid] += t;
        __syncthreads();
    }
    d_bsumblk[tid] = s[tid] - v;   // exclusive
}
__global__ void scan3_kernel() {
    __shared__ int s[256];
    int tid = threadIdx.x;
    int n = blockIdx.x * 256 + tid;
    int v = (n < NN) ? d_deg[n] : 0;
    s[tid] = v;
    __syncthreads();
    for (int o = 1; o < 256; o <<= 1) {
        int t = (tid >= o) ? s[tid - o] : 0;
        __syncthreads();
        s[tid] += t;
        __syncthreads();
    }
    if (n < NN) {
        int rp = d_bsumblk[blockIdx.x] + s[tid] - v;
        d_rowptr[n] = rp;
        d_cur[n] = rp;
    }
}
__global__ void fill_kernel(const int* __restrict__ src, const int* __restrict__ dst) {
    int e = blockIdx.x * 256 + threadIdx.x;
    if (e >= EE) return;
    int pos = atomicAdd(&d_cur[dst[e]], 1);
    d_esrc[pos] = src[e];
}

// ---------------- BN scale/shift identity ----------------
__global__ void ident_kernel() {
    int f = threadIdx.x;
    d_scale[f] = 1.f;
    d_shift[f] = 0.f;
}

// ---------------- gather: agg[n] = bn(z[n]) + sum_e bn(z[src]) (relu optional) ----------------
__device__ __forceinline__ float4 bnr4(float4 v, float4 sc, float4 sh, int relu) {
    v.x = v.x * sc.x + sh.x; v.y = v.y * sc.y + sh.y;
    v.z = v.z * sc.z + sh.z; v.w = v.w * sc.w + sh.w;
    if (relu) {
        v.x = fmaxf(v.x, 0.f); v.y = fmaxf(v.y, 0.f);
        v.z = fmaxf(v.z, 0.f); v.w = fmaxf(v.w, 0.f);
    }
    return v;
}
__global__ void __launch_bounds__(256) gather_kernel(const float* __restrict__ zin, int relu) {
    int gt = blockIdx.x * 256 + threadIdx.x;
    int w = gt >> 5, lane = gt & 31;
    if (w >= NN) return;
    int f4 = lane << 2;
    float4 sc = *(const float4*)&d_scale[f4];
    float4 sh = *(const float4*)&d_shift[f4];
    int start = d_rowptr[w];
    int deg = d_deg[w];
    float4 acc = bnr4(*(const float4*)(zin + (size_t)w * FF + f4), sc, sh, relu);
    int i = 0;
    for (; i + 2 <= deg; i += 2) {
        int s0 = d_esrc[start + i];
        int s1 = d_esrc[start + i + 1];
        float4 v0 = *(const float4*)(zin + (size_t)s0 * FF + f4);
        float4 v1 = *(const float4*)(zin + (size_t)s1 * FF + f4);
        v0 = bnr4(v0, sc, sh, relu);
        v1 = bnr4(v1, sc, sh, relu);
        acc.x += v0.x + v1.x; acc.y += v0.y + v1.y;
        acc.z += v0.z + v1.z; acc.w += v0.w + v1.w;
    }
    if (i < deg) {
        int s0 = d_esrc[start + i];
        float4 v0 = bnr4(*(const float4*)(zin + (size_t)s0 * FF + f4), sc, sh, relu);
        acc.x += v0.x; acc.y += v0.y; acc.z += v0.z; acc.w += v0.w;
    }
    *(float4*)(d_agg + (size_t)w * FF + f4) = acc;
}

// ---------------- bf16 split mma GEMM: C = relu?(A@W + b) ----------------
__global__ void __launch_bounds__(256) gemm_mma_kernel(const float* __restrict__ A,
                                                       const float* __restrict__ W,
                                                       const float* __restrict__ bias,
                                                       float* __restrict__ C,
                                                       int M, int relu) {
    extern __shared__ char sm[];
    uint32_t sb = smem_u32(sm);
    const int tid = threadIdx.x;
    const int row0 = blockIdx.x * 128;

    // W -> sWh/sWl  [k][n] padded rows
    for (int i = tid; i < 4096; i += 256) {
        int k = i >> 5, c4 = (i & 31) << 2;
        float4 v = *(const float4*)(W + (size_t)k * FF + c4);
        uint32_t h0, l0, h1, l1, h2, l2, h3, l3;
        split1(v.x, h0, l0); split1(v.y, h1, l1);
        split1(v.z, h2, l2); split1(v.w, h3, l3);
        uint32_t off = (uint32_t)k * RSTRIDE + (c4 << 1);
        *(uint2*)(sm + O_WH + off) = make_uint2(h0 | (h1 << 16), h2 | (h3 << 16));
        *(uint2*)(sm + O_WL + off) = make_uint2(l0 | (l1 << 16), l2 | (l3 << 16));
    }
    // A -> sAh/sAl  [m][k] padded rows
    for (int i = tid; i < 4096; i += 256) {
        int m = i >> 5, c4 = (i & 31) << 2;
        int r = row0 + m; if (r >= M) r = M - 1;
        float4 v = *(const float4*)(A + (size_t)r * FF + c4);
        uint32_t h0, l0, h1, l1, h2, l2, h3, l3;
        split1(v.x, h0, l0); split1(v.y, h1, l1);
        split1(v.z, h2, l2); split1(v.w, h3, l3);
        uint32_t off = (uint32_t)m * RSTRIDE + (c4 << 1);
        *(uint2*)(sm + O_AH + off) = make_uint2(h0 | (h1 << 16), h2 | (h3 << 16));
        *(uint2*)(sm + O_AL + off) = make_uint2(l0 | (l1 << 16), l2 | (l3 << 16));
    }
    __syncthreads();

    const int wid = tid >> 5, lane = tid & 31;
    const int mw = (wid & 1) << 6;    // 0 / 64
    const int nw = (wid >> 1) << 5;   // 0/32/64/96
    const int lane15 = lane & 15, lhi = lane >> 4;

    float c[4][4][4];
#pragma unroll
    for (int a = 0; a < 4; a++)
#pragma unroll
        for (int b = 0; b < 4; b++)
#pragma unroll
            for (int d = 0; d < 4; d++) c[a][b][d] = 0.f;

    uint32_t baseA = sb + O_AH + (uint32_t)(mw + lane15) * RSTRIDE + (lhi << 4);
    uint32_t baseB = sb + O_WH + (uint32_t)lane15 * RSTRIDE + (nw << 1) + (lhi << 4);

    for (int ks = 0; ks < 8; ks++) {
        uint32_t ah[4][4], al[4][4];
#pragma unroll
        for (int mt = 0; mt < 4; mt++) {
            uint32_t ad = baseA + mt * (16 * RSTRIDE) + ks * 32;
            ldsm4(ah[mt], ad);
            ldsm4(al[mt], ad + (O_AL - O_AH));
        }
        uint32_t bh[4][2], bl[4][2];
#pragma unroll
        for (int half = 0; half < 2; half++) {
            uint32_t bd = baseB + ks * (16 * RSTRIDE) + half * 32;
            uint32_t r4[4];
            ldsm4t(r4, bd);
            bh[half * 2][0] = r4[0]; bh[half * 2][1] = r4[1];
            bh[half * 2 + 1][0] = r4[2]; bh[half * 2 + 1][1] = r4[3];
            ldsm4t(r4, bd + (O_WL - O_WH));
            bl[half * 2][0] = r4[0]; bl[half * 2][1] = r4[1];
            bl[half * 2 + 1][0] = r4[2]; bl[half * 2 + 1][1] = r4[3];
        }
#pragma unroll
        for (int mt = 0; mt < 4; mt++)
#pragma unroll
            for (int nt = 0; nt < 4; nt++) {
                mma_bf16(c[mt][nt], ah[mt], bh[nt]);
                mma_bf16(c[mt][nt], ah[mt], bl[nt]);
                mma_bf16(c[mt][nt], al[mt], bh[nt]);
            }
    }

    // epilogue
    const int rr = lane >> 2, cc = (lane & 3) << 1;
#pragma unroll
    for (int mt = 0; mt < 4; mt++) {
        int gr0 = row0 + mw + mt * 16 + rr;
        int gr1 = gr0 + 8;
#pragma unroll
        for (int nt = 0; nt < 4; nt++) {
            int gc = nw + nt * 8 + cc;
            float bx = bias[gc], by = bias[gc + 1];
            float v0 = c[mt][nt][0] + bx, v1 = c[mt][nt][1] + by;
            float v2 = c[mt][nt][2] + bx, v3 = c[mt][nt][3] + by;
            if (relu) {
                v0 = fmaxf(v0, 0.f); v1 = fmaxf(v1, 0.f);
                v2 = fmaxf(v2, 0.f); v3 = fmaxf(v3, 0.f);
            }
            if (gr0 < M) *(float2*)(C + (size_t)gr0 * FF + gc) = make_float2(v0, v1);
            if (gr1 < M) *(float2*)(C + (size_t)gr1 * FF + gc) = make_float2(v2, v3);
        }
    }
}

// ---------------- BN stats ----------------
__global__ void __launch_bounds__(128) bn_stats_kernel(const float* __restrict__ z) {
    int f = threadIdx.x;
    int per = (NN + gridDim.x - 1) / gridDim.x;
    int n0 = blockIdx.x * per;
    int n1 = n0 + per; if (n1 > NN) n1 = NN;
    float s = 0.f, q = 0.f;
    for (int n = n0; n < n1; n++) {
        float v = z[(size_t)n * FF + f];
        s += v; q += v * v;
    }
    atomicAdd(&d_bsum[f], s);
    atomicAdd(&d_bsq[f], q);
}
__global__ void bn_fin_kernel(const float* __restrict__ g, const float* __restrict__ be) {
    int f = threadIdx.x;
    float mu  = d_bsum[f] * (1.0f / NN);
    float var = d_bsq[f]  * (1.0f / NN) - mu * mu;
    float sc = g[f] * rsqrtf(var + BN_EPS);
    d_scale[f] = sc;
    d_shift[f] = be[f] - mu * sc;
    d_bsum[f] = 0.f;
    d_bsq[f]  = 0.f;
}

// ---------------- concat head0 W1/b1 ----------------
__global__ void prep_cat_kernel(const float* __restrict__ W1, const float* __restrict__ b1) {
    int idx = blockIdx.x * 256 + threadIdx.x;
    if (idx < FF * FF) {
        int i = idx >> 7, c = idx & 127;
        int k = c >> 4, j = c & 15;
        d_Wcat[idx] = W1[k * (FF * DD) + i * DD + j];
    }
    if (idx < FF) {
        int k = idx >> 4, j = idx & 15;
        d_bcat[idx] = b1[k * DD + j];
    }
}

// ---------------- block-diag 16x16 single ----------------
__global__ void __launch_bounds__(256) bdiag1_kernel(const float* __restrict__ X,
                                                     const float* __restrict__ W,
                                                     const float* __restrict__ B,
                                                     float* __restrict__ C) {
    __shared__ float sW[8 * 257];
    __shared__ float sB[128];
    int tid = threadIdx.x;
    for (int i = tid; i < 2048; i += 256) sW[(i >> 8) * 257 + (i & 255)] = W[i];
    if (tid < 128) sB[tid] = B[tid];
    __syncthreads();
    int k = tid & 7;
    int n = blockIdx.x * 32 + (tid >> 3);
    if (n >= NN) return;
    const float4* xp = (const float4*)(X + (size_t)n * FF + k * DD);
    float x[16];
#pragma unroll
    for (int i = 0; i < 4; i++) {
        float4 v = xp[i];
        x[4*i] = v.x; x[4*i+1] = v.y; x[4*i+2] = v.z; x[4*i+3] = v.w;
    }
    const float* wk = sW + k * 257;
    float o[16];
#pragma unroll
    for (int j = 0; j < 16; j++) o[j] = sB[k * 16 + j];
#pragma unroll
    for (int i = 0; i < 16; i++) {
        float xi = x[i];
#pragma unroll
        for (int j = 0; j < 16; j++) o[j] += xi * wk[i * 16 + j];
    }
    float4* cp = (float4*)(C + (size_t)n * FF + k * DD);
#pragma unroll
    for (int i = 0; i < 4; i++)
        cp[i] = make_float4(o[4*i], o[4*i+1], o[4*i+2], o[4*i+3]);
}

// ---------------- block-diag double ----------------
__global__ void __launch_bounds__(256) bdiag2_kernel(const float* __restrict__ X,
                                                     const float* __restrict__ W1,
                                                     const float* __restrict__ B1,
                                                     const float* __restrict__ W2,
                                                     const float* __restrict__ B2,
                                                     float* __restrict__ C) {
    __shared__ float sW1[8 * 257];
    __shared__ float sW2[8 * 257];
    __shared__ float sB1[128];
    __shared__ float sB2[128];
    int tid = threadIdx.x;
    for (int i = tid; i < 2048; i += 256) {
        sW1[(i >> 8) * 257 + (i & 255)] = W1[i];
        sW2[(i >> 8) * 257 + (i & 255)] = W2[i];
    }
    if (tid < 128) { sB1[tid] = B1[tid]; sB2[tid] = B2[tid]; }
    __syncthreads();
    int k = tid & 7;
    int n = blockIdx.x * 32 + (tid >> 3);
    if (n >= NN) return;
    const float4* xp = (const float4*)(X + (size_t)n * FF + k * DD);
    float x[16];
#pragma unroll
    for (int i = 0; i < 4; i++) {
        float4 v = xp[i];
        x[4*i] = v.x; x[4*i+1] = v.y; x[4*i+2] = v.z; x[4*i+3] = v.w;
    }
    const float* w1 = sW1 + k * 257;
    const float* w2 = sW2 + k * 257;
    float t[16];
#pragma unroll
    for (int j = 0; j < 16; j++) t[j] = sB1[k * 16 + j];
#pragma unroll
    for (int i = 0; i < 16; i++) {
        float xi = x[i];
#pragma unroll
        for (int j = 0; j < 16; j++) t[j] += xi * w1[i * 16 + j];
    }
#pragma unroll
    for (int j = 0; j < 16; j++) t[j] = fmaxf(t[j], 0.f);
    float o[16];
#pragma unroll
    for (int j = 0; j < 16; j++) o[j] = sB2[k * 16 + j];
#pragma unroll
    for (int i = 0; i < 16; i++) {
        float ti = t[i];
#pragma unroll
        for (int j = 0; j < 16; j++) o[j] += ti * w2[i * 16 + j];
    }
    float4* cp = (float4*)(C + (size_t)n * FF + k * DD);
#pragma unroll
    for (int i = 0; i < 4; i++)
        cp[i] = make_float4(o[4*i], o[4*i+1], o[4*i+2], o[4*i+3]);
}

// ---------------- pooling (applies final BN on the fly) ----------------
__global__ void zero_out_kernel(float* __restrict__ out) {
    int idx = blockIdx.x * 256 + threadIdx.x;
    if (idx < GG * FF) out[idx] = 0.f;
}
__global__ void __launch_bounds__(256) pool_kernel(const float* __restrict__ z,
                                                   const int* __restrict__ batch,
                                                   float* __restrict__ out) {
    int idx = blockIdx.x * 256 + threadIdx.x;
    if (idx >= NN * 32) return;
    int n = idx >> 5;
    int f4 = (idx & 31) << 2;
    int g = batch[n];
    float4 v = *(const float4*)(z + (size_t)n * FF + f4);
    float4 sc = *(const float4*)&d_scale[f4];
    float4 sh = *(const float4*)&d_shift[f4];
    v.x = v.x * sc.x + sh.x; v.y = v.y * sc.y + sh.y;
    v.z = v.z * sc.z + sh.z; v.w = v.w * sc.w + sh.w;
    float* op = out + (size_t)g * FF + f4;
    asm volatile("red.global.add.v4.f32 [%0], {%1,%2,%3,%4};"
                 :: "l"(op), "f"(v.x), "f"(v.y), "f"(v.z), "f"(v.w) : "memory");
}

// ---------------- host orchestration ----------------
extern "C" void kernel_launch(void* const* d_in, const int* in_sizes, int n_in,
                              void* d_out, int out_size) {
    const float* x     = (const float*)d_in[0];
    const int*   ei    = (const int*)d_in[1];
    const int*   batch = (const int*)d_in[2];
    const float* gc_W1 = (const float*)d_in[4];
    const float* gc_b1 = (const float*)d_in[5];
    const float* gc_W2 = (const float*)d_in[6];
    const float* gc_b2 = (const float*)d_in[7];
    const float* gc_g  = (const float*)d_in[8];
    const float* gc_be = (const float*)d_in[9];
    const float* h0_W1 = (const float*)d_in[10];
    const float* h0_b1 = (const float*)d_in[11];
    const float* h0_W2 = (const float*)d_in[12];
    const float* h0_b2 = (const float*)d_in[13];
    const float* h0_g  = (const float*)d_in[14];
    const float* h0_be = (const float*)d_in[15];
    const float* h1_W1 = (const float*)d_in[16];
    const float* h1_b1 = (const float*)d_in[17];
    const float* h1_W2 = (const float*)d_in[18];
    const float* h1_b2 = (const float*)d_in[19];
    const float* h1_g  = (const float*)d_in[20];
    const float* h1_be = (const float*)d_in[21];
    float* out = (float*)d_out;

    const int* src = ei;
    const int* dst = ei + EE;

    float *pagg, *pt, *pz, *pWcat, *pbcat;
    cudaGetSymbolAddress((void**)&pagg, d_agg);
    cudaGetSymbolAddress((void**)&pt, d_t);
    cudaGetSymbolAddress((void**)&pz, d_z);
    cudaGetSymbolAddress((void**)&pWcat, d_Wcat);
    cudaGetSymbolAddress((void**)&pbcat, d_bcat);

    cudaFuncSetAttribute(gemm_mma_kernel, cudaFuncAttributeMaxDynamicSharedMemorySize, SM_TOTAL);

    const int grid_nf   = (NN * 32 + 255) / 256;   // 6250 (also gather: 1 warp/node)
    const int grid_e    = (EE + 255) / 256;        // 3125
    const int grid_gemm = (NN + 127) / 128;        // 391
    const int grid_bd   = (NN + 31) / 32;          // 1563

    // CSR build (per launch; deterministic work)
    zero_deg_kernel<<<NB, 256>>>();
    hist_kernel<<<grid_e, 256>>>(dst);
    scan1_kernel<<<NB, 256>>>();
    scan2_kernel<<<1, 256>>>();
    scan3_kernel<<<NB, 256>>>();
    fill_kernel<<<grid_e, 256>>>(src, dst);

    // layer 0 input: identity BN on x
    ident_kernel<<<1, 128>>>();
    gather_kernel<<<grid_nf, 256>>>(x, 0);

    for (int i = 0; i < GC; i++) {
        gemm_mma_kernel<<<grid_gemm, 256, SM_TOTAL>>>(pagg, gc_W1 + i * FF * FF, gc_b1 + i * FF, pt, NN, 1);
        gemm_mma_kernel<<<grid_gemm, 256, SM_TOTAL>>>(pt,   gc_W2 + i * FF * FF, gc_b2 + i * FF, pz, NN, 0);
        bn_stats_kernel<<<416, 128>>>(pz);
        bn_fin_kernel<<<1, 128>>>(gc_g + i * FF, gc_be + i * FF);
        // next layer's aggregation consumes bn(z) (+relu except after last gc layer)
        gather_kernel<<<grid_nf, 256>>>(pz, (i < GC - 1) ? 1 : 0);
    }

    // head layer 0
    prep_cat_kernel<<<64, 256>>>(h0_W1, h0_b1);
    gemm_mma_kernel<<<grid_gemm, 256, SM_TOTAL>>>(pagg, pWcat, pbcat, pt, NN, 1);
    bdiag1_kernel<<<grid_bd, 256>>>(pt, h0_W2, h0_b2, pz);
    bn_stats_kernel<<<416, 128>>>(pz);
    bn_fin_kernel<<<1, 128>>>(h0_g, h0_be);
    gather_kernel<<<grid_nf, 256>>>(pz, 1);

    // head layer 1
    bdiag2_kernel<<<grid_bd, 256>>>(pagg, h1_W1, h1_b1, h1_W2, h1_b2, pz);
    bn_stats_kernel<<<416, 128>>>(pz);
    bn_fin_kernel<<<1, 128>>>(h1_g, h1_be);

    // pooling with final BN applied on the fly
    zero_out_kernel<<<(GG * FF + 255) / 256, 256>>>(out);
    pool_kernel<<<grid_nf, 256>>>(pz, batch, out);
}

// round 5
// speedup vs baseline: 1.5998x; 1.0385x over previous
#include <cuda_runtime.h>
#include <cuda_fp16.h>
#include <cstdint>

#define NN 50000
#define EE 800000
#define FF 128
#define KK 8
#define DD 16
#define GG 512
#define GC 3
#define BN_EPS 1e-5f
#define NB 196   // ceil(NN/256)

// ---------------- static scratch ----------------
__device__ float  d_agg[NN * FF];
__device__ float  d_t[NN * FF];
__device__ float  d_z[NN * FF];
__device__ __half d_hh[NN * FF];   // fp16 bn(z) for gather
__device__ int    d_deg[NN];
__device__ int    d_rowptr[NN];
__device__ int    d_cur[NN];
__device__ int    d_esrc[EE];
__device__ int    d_bsumblk[256];
__device__ float  d_bsum[FF];
__device__ float  d_bsq[FF];
__device__ float  d_scale[FF];
__device__ float  d_shift[FF];
__device__ float  d_Wcat[FF * FF];
__device__ float  d_bcat[FF];

// ================= helpers =================
__device__ __forceinline__ uint32_t smem_u32(const void* p) {
    uint32_t a;
    asm("{ .reg .u64 t; cvta.to.shared.u64 t, %1; cvt.u32.u64 %0, t; }" : "=r"(a) : "l"(p));
    return a;
}
__device__ __forceinline__ uint32_t h2_to_u(__half2 h) {
    return *reinterpret_cast<uint32_t*>(&h);
}
__device__ __forceinline__ float2 u_to_f2(uint32_t u) {
    __half2 h = *reinterpret_cast<__half2*>(&u);
    return __half22float2(h);
}
__device__ __forceinline__ void split1(float v, uint32_t& h, uint32_t& l) {
    uint32_t u = __float_as_uint(v);
    uint32_t hr = (u + 0x7FFFu + ((u >> 16) & 1u)) & 0xFFFF0000u;
    float hf = __uint_as_float(hr);
    float lf = v - hf;
    uint32_t ul = __float_as_uint(lf);
    h = hr >> 16;
    l = (ul + 0x7FFFu + ((ul >> 16) & 1u)) >> 16;
}
__device__ __forceinline__ void ldsm4(uint32_t* r, uint32_t addr) {
    asm volatile("ldmatrix.sync.aligned.m8n8.x4.shared.b16 {%0,%1,%2,%3}, [%4];"
                 : "=r"(r[0]), "=r"(r[1]), "=r"(r[2]), "=r"(r[3]) : "r"(addr));
}
__device__ __forceinline__ void ldsm4t(uint32_t* r, uint32_t addr) {
    asm volatile("ldmatrix.sync.aligned.m8n8.x4.trans.shared.b16 {%0,%1,%2,%3}, [%4];"
                 : "=r"(r[0]), "=r"(r[1]), "=r"(r[2]), "=r"(r[3]) : "r"(addr));
}
__device__ __forceinline__ void mma_bf16(float* c, const uint32_t* a, const uint32_t* b) {
    asm volatile(
        "mma.sync.aligned.m16n8k16.row.col.f32.bf16.bf16.f32 "
        "{%0,%1,%2,%3}, {%4,%5,%6,%7}, {%8,%9}, {%0,%1,%2,%3};"
        : "+f"(c[0]), "+f"(c[1]), "+f"(c[2]), "+f"(c[3])
        : "r"(a[0]), "r"(a[1]), "r"(a[2]), "r"(a[3]), "r"(b[0]), "r"(b[1]));
}

#define RSTRIDE 272
#define O_AH 0
#define O_AL 34816
#define O_WH 69632
#define O_WL 104448
#define SM_TOTAL 139264

// ---------------- CSR build ----------------
__global__ void zero_deg_kernel() {
    int n = blockIdx.x * 256 + threadIdx.x;
    if (n < NN) d_deg[n] = 0;
}
__global__ void hist_kernel(const int* __restrict__ dst) {
    int e = blockIdx.x * 256 + threadIdx.x;
    if (e < EE) atomicAdd(&d_deg[dst[e]], 1);
}
__global__ void scan1_kernel() {
    __shared__ int s[256];
    int n = blockIdx.x * 256 + threadIdx.x;
    s[threadIdx.x] = (n < NN) ? d_deg[n] : 0;
    __syncthreads();
    for (int o = 128; o > 0; o >>= 1) {
        if (threadIdx.x < o) s[threadIdx.x] += s[threadIdx.x + o];
        __syncthreads();
    }
    if (threadIdx.x == 0) d_bsumblk[blockIdx.x] = s[0];
}
__global__ void scan2_kernel() {
    __shared__ int s[256];
    int tid = threadIdx.x;
    int v = (tid < NB) ? d_bsumblk[tid] : 0;
    s[tid] = v;
    __syncthreads();
    for (int o = 1; o < 256; o <<= 1) {
        int t = (tid >= o) ? s[tid - o] : 0;
        __syncthreads();
        s[tid] += t;
        __syncthreads();
    }
    d_bsumblk[tid] = s[tid] - v;
}
__global__ void scan3_kernel() {
    __shared__ int s[256];
    int tid = threadIdx.x;
    int n = blockIdx.x * 256 + tid;
    int v = (n < NN) ? d_deg[n] : 0;
    s[tid] = v;
    __syncthreads();
    for (int o = 1; o < 256; o <<= 1) {
        int t = (tid >= o) ? s[tid - o] : 0;
        __syncthreads();
        s[tid] += t;
        __syncthreads();
    }
    if (n < NN) {
        int rp = d_bsumblk[blockIdx.x] + s[tid] - v;
        d_rowptr[n] = rp;
        d_cur[n] = rp;
    }
}
__global__ void fill_kernel(const int* __restrict__ src, const int* __restrict__ dst) {
    int e = blockIdx.x * 256 + threadIdx.x;
    if (e >= EE) return;
    int pos = atomicAdd(&d_cur[dst[e]], 1);
    d_esrc[pos] = src[e];
}

// ---------------- bnh: d_hh = half(bn?(z)(+relu)) ----------------
__global__ void __launch_bounds__(256) bnh_kernel(const float* __restrict__ z,
                                                  int relu, int ident) {
    int idx = blockIdx.x * 256 + threadIdx.x;    // NN*16, 8 floats each
    if (idx >= NN * 16) return;
    int f8 = (idx & 15) << 3;
    const float4* zp = (const float4*)(z + ((size_t)(idx >> 4) << 7) + f8);
    float4 v0 = zp[0], v1 = zp[1];
    if (!ident) {
        float4 sc0 = *(const float4*)&d_scale[f8], sh0 = *(const float4*)&d_shift[f8];
        float4 sc1 = *(const float4*)&d_scale[f8 + 4], sh1 = *(const float4*)&d_shift[f8 + 4];
        v0.x = v0.x * sc0.x + sh0.x; v0.y = v0.y * sc0.y + sh0.y;
        v0.z = v0.z * sc0.z + sh0.z; v0.w = v0.w * sc0.w + sh0.w;
        v1.x = v1.x * sc1.x + sh1.x; v1.y = v1.y * sc1.y + sh1.y;
        v1.z = v1.z * sc1.z + sh1.z; v1.w = v1.w * sc1.w + sh1.w;
    }
    if (relu) {
        v0.x = fmaxf(v0.x, 0.f); v0.y = fmaxf(v0.y, 0.f);
        v0.z = fmaxf(v0.z, 0.f); v0.w = fmaxf(v0.w, 0.f);
        v1.x = fmaxf(v1.x, 0.f); v1.y = fmaxf(v1.y, 0.f);
        v1.z = fmaxf(v1.z, 0.f); v1.w = fmaxf(v1.w, 0.f);
    }
    uint4 o;
    o.x = h2_to_u(__floats2half2_rn(v0.x, v0.y));
    o.y = h2_to_u(__floats2half2_rn(v0.z, v0.w));
    o.z = h2_to_u(__floats2half2_rn(v1.x, v1.y));
    o.w = h2_to_u(__floats2half2_rn(v1.z, v1.w));
    *(uint4*)(d_hh + ((size_t)(idx >> 4) << 7) + f8) = o;
}

// ---------------- gather fp16: agg[n] = hh[n] + sum_e hh[src] ----------------
__global__ void __launch_bounds__(256) gather_kernel() {
    int gt = blockIdx.x * 256 + threadIdx.x;
    int w = gt >> 5, lane = gt & 31;
    if (w >= NN) return;
    int fo = lane << 2;   // 4 halves per lane
    int start = d_rowptr[w];
    int deg = d_deg[w];
    uint2 sv = *(const uint2*)(d_hh + ((size_t)w << 7) + fo);
    float2 a = u_to_f2(sv.x);
    float2 b = u_to_f2(sv.y);
    float4 acc = make_float4(a.x, a.y, b.x, b.y);
    int i = 0;
    for (; i + 2 <= deg; i += 2) {
        int s0 = d_esrc[start + i];
        int s1 = d_esrc[start + i + 1];
        uint2 v0 = *(const uint2*)(d_hh + ((size_t)s0 << 7) + fo);
        uint2 v1 = *(const uint2*)(d_hh + ((size_t)s1 << 7) + fo);
        float2 p0 = u_to_f2(v0.x);
        float2 p1 = u_to_f2(v0.y);
        float2 p2 = u_to_f2(v1.x);
        float2 p3 = u_to_f2(v1.y);
        acc.x += p0.x + p2.x; acc.y += p0.y + p2.y;
        acc.z += p1.x + p3.x; acc.w += p1.y + p3.y;
    }
    if (i < deg) {
        int s0 = d_esrc[start + i];
        uint2 v0 = *(const uint2*)(d_hh + ((size_t)s0 << 7) + fo);
        float2 p0 = u_to_f2(v0.x);
        float2 p1 = u_to_f2(v0.y);
        acc.x += p0.x; acc.y += p0.y; acc.z += p1.x; acc.w += p1.y;
    }
    *(float4*)(d_agg + ((size_t)w << 7) + fo) = acc;
}

// ---------------- bf16 split mma GEMM, optional fused BN stats ----------------
__global__ void __launch_bounds__(256) gemm_mma_kernel(const float* __restrict__ A,
                                                       const float* __restrict__ W,
                                                       const float* __restrict__ bias,
                                                       float* __restrict__ C,
                                                       int M, int relu, int stats) {
    extern __shared__ char sm[];
    uint32_t sb = smem_u32(sm);
    const int tid = threadIdx.x;
    const int row0 = blockIdx.x * 128;

    for (int i = tid; i < 4096; i += 256) {
        int k = i >> 5, c4 = (i & 31) << 2;
        float4 v = *(const float4*)(W + (size_t)k * FF + c4);
        uint32_t h0, l0, h1, l1, h2, l2, h3, l3;
        split1(v.x, h0, l0); split1(v.y, h1, l1);
        split1(v.z, h2, l2); split1(v.w, h3, l3);
        uint32_t off = (uint32_t)k * RSTRIDE + (c4 << 1);
        *(uint2*)(sm + O_WH + off) = make_uint2(h0 | (h1 << 16), h2 | (h3 << 16));
        *(uint2*)(sm + O_WL + off) = make_uint2(l0 | (l1 << 16), l2 | (l3 << 16));
    }
    for (int i = tid; i < 4096; i += 256) {
        int m = i >> 5, c4 = (i & 31) << 2;
        int r = row0 + m; if (r >= M) r = M - 1;
        float4 v = *(const float4*)(A + (size_t)r * FF + c4);
        uint32_t h0, l0, h1, l1, h2, l2, h3, l3;
        split1(v.x, h0, l0); split1(v.y, h1, l1);
        split1(v.z, h2, l2); split1(v.w, h3, l3);
        uint32_t off = (uint32_t)m * RSTRIDE + (c4 << 1);
        *(uint2*)(sm + O_AH + off) = make_uint2(h0 | (h1 << 16), h2 | (h3 << 16));
        *(uint2*)(sm + O_AL + off) = make_uint2(l0 | (l1 << 16), l2 | (l3 << 16));
    }
    __syncthreads();

    const int wid = tid >> 5, lane = tid & 31;
    const int mw = (wid & 1) << 6;
    const int nw = (wid >> 1) << 5;
    const int lane15 = lane & 15, lhi = lane >> 4;

    float c[4][4][4];
#pragma unroll
    for (int a = 0; a < 4; a++)
#pragma unroll
        for (int b = 0; b < 4; b++)
#pragma unroll
            for (int d = 0; d < 4; d++) c[a][b][d] = 0.f;

    uint32_t baseA = sb + O_AH + (uint32_t)(mw + lane15) * RSTRIDE + (lhi << 4);
    uint32_t baseB = sb + O_WH + (uint32_t)lane15 * RSTRIDE + (nw << 1) + (lhi << 4);

    for (int ks = 0; ks < 8; ks++) {
        uint32_t ah[4][4], al[4][4];
#pragma unroll
        for (int mt = 0; mt < 4; mt++) {
            uint32_t ad = baseA + mt * (16 * RSTRIDE) + ks * 32;
            ldsm4(ah[mt], ad);
            ldsm4(al[mt], ad + (O_AL - O_AH));
        }
        uint32_t bh[4][2], bl[4][2];
#pragma unroll
        for (int half = 0; half < 2; half++) {
            uint32_t bd = baseB + ks * (16 * RSTRIDE) + half * 32;
            uint32_t r4[4];
            ldsm4t(r4, bd);
            bh[half * 2][0] = r4[0]; bh[half * 2][1] = r4[1];
            bh[half * 2 + 1][0] = r4[2]; bh[half * 2 + 1][1] = r4[3];
            ldsm4t(r4, bd + (O_WL - O_WH));
            bl[half * 2][0] = r4[0]; bl[half * 2][1] = r4[1];
            bl[half * 2 + 1][0] = r4[2]; bl[half * 2 + 1][1] = r4[3];
        }
#pragma unroll
        for (int mt = 0; mt < 4; mt++)
#pragma unroll
            for (int nt = 0; nt < 4; nt++) {
                mma_bf16(c[mt][nt], ah[mt], bh[nt]);
                mma_bf16(c[mt][nt], ah[mt], bl[nt]);
                mma_bf16(c[mt][nt], al[mt], bh[nt]);
            }
    }

    const int rr = lane >> 2, cc = (lane & 3) << 1;
    float s[4][2], q[4][2];
#pragma unroll
    for (int nt = 0; nt < 4; nt++) { s[nt][0] = s[nt][1] = q[nt][0] = q[nt][1] = 0.f; }

#pragma unroll
    for (int mt = 0; mt < 4; mt++) {
        int gr0 = row0 + mw + mt * 16 + rr;
        int gr1 = gr0 + 8;
#pragma unroll
        for (int nt = 0; nt < 4; nt++) {
            int gc = nw + nt * 8 + cc;
            float bx = bias[gc], by = bias[gc + 1];
            float v0 = c[mt][nt][0] + bx, v1 = c[mt][nt][1] + by;
            float v2 = c[mt][nt][2] + bx, v3 = c[mt][nt][3] + by;
            if (relu) {
                v0 = fmaxf(v0, 0.f); v1 = fmaxf(v1, 0.f);
                v2 = fmaxf(v2, 0.f); v3 = fmaxf(v3, 0.f);
            }
            if (gr0 < M) {
                *(float2*)(C + (size_t)gr0 * FF + gc) = make_float2(v0, v1);
                if (stats) { s[nt][0] += v0; q[nt][0] += v0 * v0; s[nt][1] += v1; q[nt][1] += v1 * v1; }
            }
            if (gr1 < M) {
                *(float2*)(C + (size_t)gr1 * FF + gc) = make_float2(v2, v3);
                if (stats) { s[nt][0] += v2; q[nt][0] += v2 * v2; s[nt][1] += v3; q[nt][1] += v3 * v3; }
            }
        }
    }
    if (stats) {
#pragma unroll
        for (int off = 16; off >= 4; off >>= 1) {
#pragma unroll
            for (int nt = 0; nt < 4; nt++) {
#pragma unroll
                for (int j = 0; j < 2; j++) {
                    s[nt][j] += __shfl_xor_sync(0xFFFFFFFFu, s[nt][j], off);
                    q[nt][j] += __shfl_xor_sync(0xFFFFFFFFu, q[nt][j], off);
                }
            }
        }
        if (lane < 4) {
#pragma unroll
            for (int nt = 0; nt < 4; nt++) {
                int gc = nw + nt * 8 + (lane << 1);
                atomicAdd(&d_bsum[gc], s[nt][0]);
                atomicAdd(&d_bsum[gc + 1], s[nt][1]);
                atomicAdd(&d_bsq[gc], q[nt][0]);
                atomicAdd(&d_bsq[gc + 1], q[nt][1]);
            }
        }
    }
}

__global__ void bn_fin_kernel(const float* __restrict__ g, const float* __restrict__ be) {
    int f = threadIdx.x;
    float mu  = d_bsum[f] * (1.0f / NN);
    float var = d_bsq[f]  * (1.0f / NN) - mu * mu;
    float sc = g[f] * rsqrtf(var + BN_EPS);
    d_scale[f] = sc;
    d_shift[f] = be[f] - mu * sc;
    d_bsum[f] = 0.f;
    d_bsq[f]  = 0.f;
}

// ---------------- concat head0 W1/b1 ----------------
__global__ void prep_cat_kernel(const float* __restrict__ W1, const float* __restrict__ b1) {
    int idx = blockIdx.x * 256 + threadIdx.x;
    if (idx < FF * FF) {
        int i = idx >> 7, c = idx & 127;
        int k = c >> 4, j = c & 15;
        d_Wcat[idx] = W1[k * (FF * DD) + i * DD + j];
    }
    if (idx < FF) {
        int k = idx >> 4, j = idx & 15;
        d_bcat[idx] = b1[k * DD + j];
    }
}

// ---------------- block-diag single + fused stats (128 nodes/CTA) ----------------
__global__ void __launch_bounds__(256) bdiag1_kernel(const float* __restrict__ X,
                                                     const float* __restrict__ W,
                                                     const float* __restrict__ B,
                                                     float* __restrict__ C) {
    __shared__ float sW[8 * 257];
    __shared__ float sB[128];
    __shared__ float sSum[128], sSq[128];
    int tid = threadIdx.x;
    for (int i = tid; i < 2048; i += 256) sW[(i >> 8) * 257 + (i & 255)] = W[i];
    if (tid < 128) { sB[tid] = B[tid]; sSum[tid] = 0.f; sSq[tid] = 0.f; }
    __syncthreads();
    int k = tid & 7;
    const float* wk = sW + k * 257;
    float s[16], q[16];
#pragma unroll
    for (int j = 0; j < 16; j++) { s[j] = 0.f; q[j] = 0.f; }

    for (int it = 0; it < 4; it++) {
        int n = blockIdx.x * 128 + it * 32 + (tid >> 3);
        if (n >= NN) break;
        const float4* xp = (const float4*)(X + ((size_t)n << 7) + k * DD);
        float x[16];
#pragma unroll
        for (int i = 0; i < 4; i++) {
            float4 v = xp[i];
            x[4*i] = v.x; x[4*i+1] = v.y; x[4*i+2] = v.z; x[4*i+3] = v.w;
        }
        float o[16];
#pragma unroll
        for (int j = 0; j < 16; j++) o[j] = sB[k * 16 + j];
#pragma unroll
        for (int i = 0; i < 16; i++) {
            float xi = x[i];
#pragma unroll
            for (int j = 0; j < 16; j++) o[j] += xi * wk[i * 16 + j];
        }
        float4* cp = (float4*)(C + ((size_t)n << 7) + k * DD);
#pragma unroll
        for (int i = 0; i < 4; i++)
            cp[i] = make_float4(o[4*i], o[4*i+1], o[4*i+2], o[4*i+3]);
#pragma unroll
        for (int j = 0; j < 16; j++) { s[j] += o[j]; q[j] += o[j] * o[j]; }
    }
#pragma unroll
    for (int off = 16; off >= 8; off >>= 1) {
#pragma unroll
        for (int j = 0; j < 16; j++) {
            s[j] += __shfl_xor_sync(0xFFFFFFFFu, s[j], off);
            q[j] += __shfl_xor_sync(0xFFFFFFFFu, q[j], off);
        }
    }
    if ((tid & 31) < 8) {
#pragma unroll
        for (int j = 0; j < 16; j++) {
            atomicAdd(&sSum[k * 16 + j], s[j]);
            atomicAdd(&sSq[k * 16 + j], q[j]);
        }
    }
    __syncthreads();
    if (tid < 128) {
        atomicAdd(&d_bsum[tid], sSum[tid]);
        atomicAdd(&d_bsq[tid], sSq[tid]);
    }
}

// ---------------- block-diag double + fused stats (128 nodes/CTA) ----------------
__global__ void __launch_bounds__(256) bdiag2_kernel(const float* __restrict__ X,
                                                     const float* __restrict__ W1,
                                                     const float* __restrict__ B1,
                                                     const float* __restrict__ W2,
                                                     const float* __restrict__ B2,
                                                     float* __restrict__ C) {
    __shared__ float sW1[8 * 257];
    __shared__ float sW2[8 * 257];
    __shared__ float sB1[128];
    __shared__ float sB2[128];
    __shared__ float sSum[128], sSq[128];
    int tid = threadIdx.x;
    for (int i = tid; i < 2048; i += 256) {
        sW1[(i >> 8) * 257 + (i & 255)] = W1[i];
        sW2[(i >> 8) * 257 + (i & 255)] = W2[i];
    }
    if (tid < 128) { sB1[tid] = B1[tid]; sB2[tid] = B2[tid]; sSum[tid] = 0.f; sSq[tid] = 0.f; }
    __syncthreads();
    int k = tid & 7;
    const float* w1 = sW1 + k * 257;
    const float* w2 = sW2 + k * 257;
    float s[16], q[16];
#pragma unroll
    for (int j = 0; j < 16; j++) { s[j] = 0.f; q[j] = 0.f; }

    for (int it = 0; it < 4; it++) {
        int n = blockIdx.x * 128 + it * 32 + (tid >> 3);
        if (n >= NN) break;
        const float4* xp = (const float4*)(X + ((size_t)n << 7) + k * DD);
        float x[16];
#pragma unroll
        for (int i = 0; i < 4; i++) {
            float4 v = xp[i];
            x[4*i] = v.x; x[4*i+1] = v.y; x[4*i+2] = v.z; x[4*i+3] = v.w;
        }
        float t[16];
#pragma unroll
        for (int j = 0; j < 16; j++) t[j] = sB1[k * 16 + j];
#pragma unroll
        for (int i = 0; i < 16; i++) {
            float xi = x[i];
#pragma unroll
            for (int j = 0; j < 16; j++) t[j] += xi * w1[i * 16 + j];
        }
#pragma unroll
        for (int j = 0; j < 16; j++) t[j] = fmaxf(t[j], 0.f);
        float o[16];
#pragma unroll
        for (int j = 0; j < 16; j++) o[j] = sB2[k * 16 + j];
#pragma unroll
        for (int i = 0; i < 16; i++) {
            float ti = t[i];
#pragma unroll
            for (int j = 0; j < 16; j++) o[j] += ti * w2[i * 16 + j];
        }
        float4* cp = (float4*)(C + ((size_t)n << 7) + k * DD);
#pragma unroll
        for (int i = 0; i < 4; i++)
            cp[i] = make_float4(o[4*i], o[4*i+1], o[4*i+2], o[4*i+3]);
#pragma unroll
        for (int j = 0; j < 16; j++) { s[j] += o[j]; q[j] += o[j] * o[j]; }
    }
#pragma unroll
    for (int off = 16; off >= 8; off >>= 1) {
#pragma unroll
        for (int j = 0; j < 16; j++) {
            s[j] += __shfl_xor_sync(0xFFFFFFFFu, s[j], off);
            q[j] += __shfl_xor_sync(0xFFFFFFFFu, q[j], off);
        }
    }
    if ((tid & 31) < 8) {
#pragma unroll
        for (int j = 0; j < 16; j++) {
            atomicAdd(&sSum[k * 16 + j], s[j]);
            atomicAdd(&sSq[k * 16 + j], q[j]);
        }
    }
    __syncthreads();
    if (tid < 128) {
        atomicAdd(&d_bsum[tid], sSum[tid]);
        atomicAdd(&d_bsq[tid], sSq[tid]);
    }
}

// ---------------- pooling (applies final BN on the fly) ----------------
__global__ void zero_out_kernel(float* __restrict__ out) {
    int idx = blockIdx.x * 256 + threadIdx.x;
    if (idx < GG * FF) out[idx] = 0.f;
}
__global__ void __launch_bounds__(256) pool_kernel(const float* __restrict__ z,
                                                   const int* __restrict__ batch,
                                                   float* __restrict__ out) {
    int idx = blockIdx.x * 256 + threadIdx.x;
    if (idx >= NN * 32) return;
    int n = idx >> 5;
    int f4 = (idx & 31) << 2;
    int g = batch[n];
    float4 v = *(const float4*)(z + ((size_t)n << 7) + f4);
    float4 sc = *(const float4*)&d_scale[f4];
    float4 sh = *(const float4*)&d_shift[f4];
    v.x = v.x * sc.x + sh.x; v.y = v.y * sc.y + sh.y;
    v.z = v.z * sc.z + sh.z; v.w = v.w * sc.w + sh.w;
    float* op = out + (size_t)g * FF + f4;
    asm volatile("red.global.add.v4.f32 [%0], {%1,%2,%3,%4};"
                 :: "l"(op), "f"(v.x), "f"(v.y), "f"(v.z), "f"(v.w) : "memory");
}

// ---------------- host orchestration ----------------
extern "C" void kernel_launch(void* const* d_in, const int* in_sizes, int n_in,
                              void* d_out, int out_size) {
    const float* x     = (const float*)d_in[0];
    const int*   ei    = (const int*)d_in[1];
    const int*   batch = (const int*)d_in[2];
    const float* gc_W1 = (const float*)d_in[4];
    const float* gc_b1 = (const float*)d_in[5];
    const float* gc_W2 = (const float*)d_in[6];
    const float* gc_b2 = (const float*)d_in[7];
    const float* gc_g  = (const float*)d_in[8];
    const float* gc_be = (const float*)d_in[9];
    const float* h0_W1 = (const float*)d_in[10];
    const float* h0_b1 = (const float*)d_in[11];
    const float* h0_W2 = (const float*)d_in[12];
    const float* h0_b2 = (const float*)d_in[13];
    const float* h0_g  = (const float*)d_in[14];
    const float* h0_be = (const float*)d_in[15];
    const float* h1_W1 = (const float*)d_in[16];
    const float* h1_b1 = (const float*)d_in[17];
    const float* h1_W2 = (const float*)d_in[18];
    const float* h1_b2 = (const float*)d_in[19];
    const float* h1_g  = (const float*)d_in[20];
    const float* h1_be = (const float*)d_in[21];
    float* out = (float*)d_out;

    const int* src = ei;
    const int* dst = ei + EE;

    float *pagg, *pt, *pz, *pWcat, *pbcat;
    cudaGetSymbolAddress((void**)&pagg, d_agg);
    cudaGetSymbolAddress((void**)&pt, d_t);
    cudaGetSymbolAddress((void**)&pz, d_z);
    cudaGetSymbolAddress((void**)&pWcat, d_Wcat);
    cudaGetSymbolAddress((void**)&pbcat, d_bcat);

    cudaFuncSetAttribute(gemm_mma_kernel, cudaFuncAttributeMaxDynamicSharedMemorySize, SM_TOTAL);

    const int grid_nf   = (NN * 32 + 255) / 256;
    const int grid_cv   = (NN * 16 + 255) / 256;
    const int grid_e    = (EE + 255) / 256;
    const int grid_gemm = (NN + 127) / 128;
    const int grid_bd   = (NN + 127) / 128;

    // CSR build
    zero_deg_kernel<<<NB, 256>>>();
    hist_kernel<<<grid_e, 256>>>(dst);
    scan1_kernel<<<NB, 256>>>();
    scan2_kernel<<<1, 256>>>();
    scan3_kernel<<<NB, 256>>>();
    fill_kernel<<<grid_e, 256>>>(src, dst);

    // layer 0 input: x -> fp16 (identity), gather
    bnh_kernel<<<grid_cv, 256>>>(x, 0, 1);
    gather_kernel<<<grid_nf, 256>>>();

    for (int i = 0; i < GC; i++) {
        gemm_mma_kernel<<<grid_gemm, 256, SM_TOTAL>>>(pagg, gc_W1 + i * FF * FF, gc_b1 + i * FF, pt, NN, 1, 0);
        gemm_mma_kernel<<<grid_gemm, 256, SM_TOTAL>>>(pt,   gc_W2 + i * FF * FF, gc_b2 + i * FF, pz, NN, 0, 1);
        bn_fin_kernel<<<1, 128>>>(gc_g + i * FF, gc_be + i * FF);
        bnh_kernel<<<grid_cv, 256>>>(pz, (i < GC - 1) ? 1 : 0, 0);
        gather_kernel<<<grid_nf, 256>>>();
    }

    // head layer 0
    prep_cat_kernel<<<64, 256>>>(h0_W1, h0_b1);
    gemm_mma_kernel<<<grid_gemm, 256, SM_TOTAL>>>(pagg, pWcat, pbcat, pt, NN, 1, 0);
    bdiag1_kernel<<<grid_bd, 256>>>(pt, h0_W2, h0_b2, pz);
    bn_fin_kernel<<<1, 128>>>(h0_g, h0_be);
    bnh_kernel<<<grid_cv, 256>>>(pz, 1, 0);
    gather_kernel<<<grid_nf, 256>>>();

    // head layer 1
    bdiag2_kernel<<<grid_bd, 256>>>(pagg, h1_W1, h1_b1, h1_W2, h1_b2, pz);
    bn_fin_kernel<<<1, 128>>>(h1_g, h1_be);

    // pooling with final BN applied on the fly
    zero_out_kernel<<<(GG * FF + 255) / 256, 256>>>(out);
    pool_kernel<<<grid_nf, 256>>>(pz, batch, out);
}

// round 6
// speedup vs baseline: 1.6143x; 1.0091x over previous
#include <cuda_runtime.h>
#include <cuda_fp16.h>
#include <cstdint>

#define NN 50000
#define EE 800000
#define FF 128
#define KK 8
#define DD 16
#define GG 512
#define GC 3
#define BN_EPS 1e-5f
#define NB 196   // ceil(NN/256)

// ---------------- static scratch ----------------
__device__ float  d_agg[NN * FF];
__device__ float  d_t[NN * FF];
__device__ float  d_z[NN * FF];
__device__ __half d_hh[NN * FF];   // fp16 bn(z) for gather
__device__ int    d_deg[NN];
__device__ int    d_rowptr[NN];
__device__ int    d_cur[NN];
__device__ int    d_esrc[EE];
__device__ int    d_bsumblk[256];
__device__ float  d_bsum[FF];
__device__ float  d_bsq[FF];
__device__ float  d_scale[FF];
__device__ float  d_shift[FF];
__device__ float  d_Wcat[FF * FF];
__device__ float  d_bcat[FF];

// ================= helpers =================
__device__ __forceinline__ uint32_t smem_u32(const void* p) {
    uint32_t a;
    asm("{ .reg .u64 t; cvta.to.shared.u64 t, %1; cvt.u32.u64 %0, t; }" : "=r"(a) : "l"(p));
    return a;
}
__device__ __forceinline__ uint32_t h2_to_u(__half2 h) {
    return *reinterpret_cast<uint32_t*>(&h);
}
__device__ __forceinline__ float2 u_to_f2(uint32_t u) {
    __half2 h = *reinterpret_cast<__half2*>(&u);
    return __half22float2(h);
}
__device__ __forceinline__ void split1(float v, uint32_t& h, uint32_t& l) {
    uint32_t u = __float_as_uint(v);
    uint32_t hr = (u + 0x7FFFu + ((u >> 16) & 1u)) & 0xFFFF0000u;
    float hf = __uint_as_float(hr);
    float lf = v - hf;
    uint32_t ul = __float_as_uint(lf);
    h = hr >> 16;
    l = (ul + 0x7FFFu + ((ul >> 16) & 1u)) >> 16;
}
__device__ __forceinline__ void ldsm4(uint32_t* r, uint32_t addr) {
    asm volatile("ldmatrix.sync.aligned.m8n8.x4.shared.b16 {%0,%1,%2,%3}, [%4];"
                 : "=r"(r[0]), "=r"(r[1]), "=r"(r[2]), "=r"(r[3]) : "r"(addr));
}
__device__ __forceinline__ void ldsm4t(uint32_t* r, uint32_t addr) {
    asm volatile("ldmatrix.sync.aligned.m8n8.x4.trans.shared.b16 {%0,%1,%2,%3}, [%4];"
                 : "=r"(r[0]), "=r"(r[1]), "=r"(r[2]), "=r"(r[3]) : "r"(addr));
}
__device__ __forceinline__ void mma_bf16(float* c, const uint32_t* a, const uint32_t* b) {
    asm volatile(
        "mma.sync.aligned.m16n8k16.row.col.f32.bf16.bf16.f32 "
        "{%0,%1,%2,%3}, {%4,%5,%6,%7}, {%8,%9}, {%0,%1,%2,%3};"
        : "+f"(c[0]), "+f"(c[1]), "+f"(c[2]), "+f"(c[3])
        : "r"(a[0]), "r"(a[1]), "r"(a[2]), "r"(a[3]), "r"(b[0]), "r"(b[1]));
}
__device__ __forceinline__ void add8(float* acc, uint4 v) {
    float2 p0 = u_to_f2(v.x), p1 = u_to_f2(v.y), p2 = u_to_f2(v.z), p3 = u_to_f2(v.w);
    acc[0] += p0.x; acc[1] += p0.y; acc[2] += p1.x; acc[3] += p1.y;
    acc[4] += p2.x; acc[5] += p2.y; acc[6] += p3.x; acc[7] += p3.y;
}

#define RSTRIDE 272
#define O_AH 0
#define O_AL 34816
#define O_WH 69632
#define O_WL 104448
#define SM_TOTAL 139264

// ---------------- CSR build ----------------
__global__ void zero_deg_kernel() {
    int n = blockIdx.x * 256 + threadIdx.x;
    if (n < NN) d_deg[n] = 0;
}
__global__ void hist_kernel(const int* __restrict__ dst) {
    int e = blockIdx.x * 256 + threadIdx.x;
    if (e < EE) atomicAdd(&d_deg[dst[e]], 1);
}
__global__ void scan1_kernel() {
    __shared__ int s[256];
    int n = blockIdx.x * 256 + threadIdx.x;
    s[threadIdx.x] = (n < NN) ? d_deg[n] : 0;
    __syncthreads();
    for (int o = 128; o > 0; o >>= 1) {
        if (threadIdx.x < o) s[threadIdx.x] += s[threadIdx.x + o];
        __syncthreads();
    }
    if (threadIdx.x == 0) d_bsumblk[blockIdx.x] = s[0];
}
__global__ void scan2_kernel() {
    __shared__ int s[256];
    int tid = threadIdx.x;
    int v = (tid < NB) ? d_bsumblk[tid] : 0;
    s[tid] = v;
    __syncthreads();
    for (int o = 1; o < 256; o <<= 1) {
        int t = (tid >= o) ? s[tid - o] : 0;
        __syncthreads();
        s[tid] += t;
        __syncthreads();
    }
    d_bsumblk[tid] = s[tid] - v;
}
__global__ void scan3_kernel() {
    __shared__ int s[256];
    int tid = threadIdx.x;
    int n = blockIdx.x * 256 + tid;
    int v = (n < NN) ? d_deg[n] : 0;
    s[tid] = v;
    __syncthreads();
    for (int o = 1; o < 256; o <<= 1) {
        int t = (tid >= o) ? s[tid - o] : 0;
        __syncthreads();
        s[tid] += t;
        __syncthreads();
    }
    if (n < NN) {
        int rp = d_bsumblk[blockIdx.x] + s[tid] - v;
        d_rowptr[n] = rp;
        d_cur[n] = rp;
    }
}
__global__ void fill_kernel(const int* __restrict__ src, const int* __restrict__ dst) {
    int e = blockIdx.x * 256 + threadIdx.x;
    if (e >= EE) return;
    int pos = atomicAdd(&d_cur[dst[e]], 1);
    d_esrc[pos] = src[e];
}

// ---------------- bnh: d_hh = half(bn?(z)(+relu)) ----------------
__global__ void __launch_bounds__(256) bnh_kernel(const float* __restrict__ z,
                                                  int relu, int ident) {
    int idx = blockIdx.x * 256 + threadIdx.x;    // NN*16, 8 floats each
    if (idx >= NN * 16) return;
    int f8 = (idx & 15) << 3;
    const float4* zp = (const float4*)(z + ((size_t)(idx >> 4) << 7) + f8);
    float4 v0 = zp[0], v1 = zp[1];
    if (!ident) {
        float4 sc0 = *(const float4*)&d_scale[f8], sh0 = *(const float4*)&d_shift[f8];
        float4 sc1 = *(const float4*)&d_scale[f8 + 4], sh1 = *(const float4*)&d_shift[f8 + 4];
        v0.x = v0.x * sc0.x + sh0.x; v0.y = v0.y * sc0.y + sh0.y;
        v0.z = v0.z * sc0.z + sh0.z; v0.w = v0.w * sc0.w + sh0.w;
        v1.x = v1.x * sc1.x + sh1.x; v1.y = v1.y * sc1.y + sh1.y;
        v1.z = v1.z * sc1.z + sh1.z; v1.w = v1.w * sc1.w + sh1.w;
    }
    if (relu) {
        v0.x = fmaxf(v0.x, 0.f); v0.y = fmaxf(v0.y, 0.f);
        v0.z = fmaxf(v0.z, 0.f); v0.w = fmaxf(v0.w, 0.f);
        v1.x = fmaxf(v1.x, 0.f); v1.y = fmaxf(v1.y, 0.f);
        v1.z = fmaxf(v1.z, 0.f); v1.w = fmaxf(v1.w, 0.f);
    }
    uint4 o;
    o.x = h2_to_u(__floats2half2_rn(v0.x, v0.y));
    o.y = h2_to_u(__floats2half2_rn(v0.z, v0.w));
    o.z = h2_to_u(__floats2half2_rn(v1.x, v1.y));
    o.w = h2_to_u(__floats2half2_rn(v1.z, v1.w));
    *(uint4*)(d_hh + ((size_t)(idx >> 4) << 7) + f8) = o;
}

// ---------------- gather: warp/node, 2 edges in flight via lane halves ----------------
__global__ void __launch_bounds__(256) gather_kernel() {
    int gt = blockIdx.x * 256 + threadIdx.x;
    int w = gt >> 5, lane = gt & 31;
    if (w >= NN) return;
    int half = lane >> 4;        // 0 or 1 -> which edge of the pair
    int fo = (lane & 15) << 3;   // 8 halves per lane
    int start = d_rowptr[w];
    int deg = d_deg[w];

    float acc[8];
#pragma unroll
    for (int j = 0; j < 8; j++) acc[j] = 0.f;

    if (half == 0)
        add8(acc, *(const uint4*)(d_hh + ((size_t)w << 7) + fo));

    int i = half;
    for (; i + 2 < deg; i += 4) {       // this half does edges i and i+2
        int s0 = d_esrc[start + i];
        int s1 = d_esrc[start + i + 2];
        uint4 v0 = *(const uint4*)(d_hh + ((size_t)s0 << 7) + fo);
        uint4 v1 = *(const uint4*)(d_hh + ((size_t)s1 << 7) + fo);
        add8(acc, v0);
        add8(acc, v1);
    }
    if (i < deg) {
        int s0 = d_esrc[start + i];
        add8(acc, *(const uint4*)(d_hh + ((size_t)s0 << 7) + fo));
    }

    // merge the two lane-halves (same feature slice in lane and lane^16)
#pragma unroll
    for (int j = 0; j < 8; j++)
        acc[j] += __shfl_xor_sync(0xFFFFFFFFu, acc[j], 16);

    if (half == 0) {
        float* op = d_agg + ((size_t)w << 7) + fo;
        *(float4*)op       = make_float4(acc[0], acc[1], acc[2], acc[3]);
        *(float4*)(op + 4) = make_float4(acc[4], acc[5], acc[6], acc[7]);
    }
}

// ---------------- bf16 split mma GEMM, optional fused BN stats ----------------
__global__ void __launch_bounds__(256) gemm_mma_kernel(const float* __restrict__ A,
                                                       const float* __restrict__ W,
                                                       const float* __restrict__ bias,
                                                       float* __restrict__ C,
                                                       int M, int relu, int stats) {
    extern __shared__ char sm[];
    uint32_t sb = smem_u32(sm);
    const int tid = threadIdx.x;
    const int row0 = blockIdx.x * 128;

    for (int i = tid; i < 4096; i += 256) {
        int k = i >> 5, c4 = (i & 31) << 2;
        float4 v = *(const float4*)(W + (size_t)k * FF + c4);
        uint32_t h0, l0, h1, l1, h2, l2, h3, l3;
        split1(v.x, h0, l0); split1(v.y, h1, l1);
        split1(v.z, h2, l2); split1(v.w, h3, l3);
        uint32_t off = (uint32_t)k * RSTRIDE + (c4 << 1);
        *(uint2*)(sm + O_WH + off) = make_uint2(h0 | (h1 << 16), h2 | (h3 << 16));
        *(uint2*)(sm + O_WL + off) = make_uint2(l0 | (l1 << 16), l2 | (l3 << 16));
    }
    for (int i = tid; i < 4096; i += 256) {
        int m = i >> 5, c4 = (i & 31) << 2;
        int r = row0 + m; if (r >= M) r = M - 1;
        float4 v = *(const float4*)(A + (size_t)r * FF + c4);
        uint32_t h0, l0, h1, l1, h2, l2, h3, l3;
        split1(v.x, h0, l0); split1(v.y, h1, l1);
        split1(v.z, h2, l2); split1(v.w, h3, l3);
        uint32_t off = (uint32_t)m * RSTRIDE + (c4 << 1);
        *(uint2*)(sm + O_AH + off) = make_uint2(h0 | (h1 << 16), h2 | (h3 << 16));
        *(uint2*)(sm + O_AL + off) = make_uint2(l0 | (l1 << 16), l2 | (l3 << 16));
    }
    __syncthreads();

    const int wid = tid >> 5, lane = tid & 31;
    const int mw = (wid & 1) << 6;
    const int nw = (wid >> 1) << 5;
    const int lane15 = lane & 15, lhi = lane >> 4;

    float c[4][4][4];
#pragma unroll
    for (int a = 0; a < 4; a++)
#pragma unroll
        for (int b = 0; b < 4; b++)
#pragma unroll
            for (int d = 0; d < 4; d++) c[a][b][d] = 0.f;

    uint32_t baseA = sb + O_AH + (uint32_t)(mw + lane15) * RSTRIDE + (lhi << 4);
    uint32_t baseB = sb + O_WH + (uint32_t)lane15 * RSTRIDE + (nw << 1) + (lhi << 4);

    for (int ks = 0; ks < 8; ks++) {
        uint32_t ah[4][4], al[4][4];
#pragma unroll
        for (int mt = 0; mt < 4; mt++) {
            uint32_t ad = baseA + mt * (16 * RSTRIDE) + ks * 32;
            ldsm4(ah[mt], ad);
            ldsm4(al[mt], ad + (O_AL - O_AH));
        }
        uint32_t bh[4][2], bl[4][2];
#pragma unroll
        for (int half = 0; half < 2; half++) {
            uint32_t bd = baseB + ks * (16 * RSTRIDE) + half * 32;
            uint32_t r4[4];
            ldsm4t(r4, bd);
            bh[half * 2][0] = r4[0]; bh[half * 2][1] = r4[1];
            bh[half * 2 + 1][0] = r4[2]; bh[half * 2 + 1][1] = r4[3];
            ldsm4t(r4, bd + (O_WL - O_WH));
            bl[half * 2][0] = r4[0]; bl[half * 2][1] = r4[1];
            bl[half * 2 + 1][0] = r4[2]; bl[half * 2 + 1][1] = r4[3];
        }
#pragma unroll
        for (int mt = 0; mt < 4; mt++)
#pragma unroll
            for (int nt = 0; nt < 4; nt++) {
                mma_bf16(c[mt][nt], ah[mt], bh[nt]);
                mma_bf16(c[mt][nt], ah[mt], bl[nt]);
                mma_bf16(c[mt][nt], al[mt], bh[nt]);
            }
    }

    const int rr = lane >> 2, cc = (lane & 3) << 1;
    float s[4][2], q[4][2];
#pragma unroll
    for (int nt = 0; nt < 4; nt++) { s[nt][0] = s[nt][1] = q[nt][0] = q[nt][1] = 0.f; }

#pragma unroll
    for (int mt = 0; mt < 4; mt++) {
        int gr0 = row0 + mw + mt * 16 + rr;
        int gr1 = gr0 + 8;
#pragma unroll
        for (int nt = 0; nt < 4; nt++) {
            int gc = nw + nt * 8 + cc;
            float bx = bias[gc], by = bias[gc + 1];
            float v0 = c[mt][nt][0] + bx, v1 = c[mt][nt][1] + by;
            float v2 = c[mt][nt][2] + bx, v3 = c[mt][nt][3] + by;
            if (relu) {
                v0 = fmaxf(v0, 0.f); v1 = fmaxf(v1, 0.f);
                v2 = fmaxf(v2, 0.f); v3 = fmaxf(v3, 0.f);
            }
            if (gr0 < M) {
                *(float2*)(C + (size_t)gr0 * FF + gc) = make_float2(v0, v1);
                if (stats) { s[nt][0] += v0; q[nt][0] += v0 * v0; s[nt][1] += v1; q[nt][1] += v1 * v1; }
            }
            if (gr1 < M) {
                *(float2*)(C + (size_t)gr1 * FF + gc) = make_float2(v2, v3);
                if (stats) { s[nt][0] += v2; q[nt][0] += v2 * v2; s[nt][1] += v3; q[nt][1] += v3 * v3; }
            }
        }
    }
    if (stats) {
#pragma unroll
        for (int off = 16; off >= 4; off >>= 1) {
#pragma unroll
            for (int nt = 0; nt < 4; nt++) {
#pragma unroll
                for (int j = 0; j < 2; j++) {
                    s[nt][j] += __shfl_xor_sync(0xFFFFFFFFu, s[nt][j], off);
                    q[nt][j] += __shfl_xor_sync(0xFFFFFFFFu, q[nt][j], off);
                }
            }
        }
        if (lane < 4) {
#pragma unroll
            for (int nt = 0; nt < 4; nt++) {
                int gc = nw + nt * 8 + (lane << 1);
                atomicAdd(&d_bsum[gc], s[nt][0]);
                atomicAdd(&d_bsum[gc + 1], s[nt][1]);
                atomicAdd(&d_bsq[gc], q[nt][0]);
                atomicAdd(&d_bsq[gc + 1], q[nt][1]);
            }
        }
    }
}

__global__ void bn_fin_kernel(const float* __restrict__ g, const float* __restrict__ be) {
    int f = threadIdx.x;
    float mu  = d_bsum[f] * (1.0f / NN);
    float var = d_bsq[f]  * (1.0f / NN) - mu * mu;
    float sc = g[f] * rsqrtf(var + BN_EPS);
    d_scale[f] = sc;
    d_shift[f] = be[f] - mu * sc;
    d_bsum[f] = 0.f;
    d_bsq[f]  = 0.f;
}

// ---------------- concat head0 W1/b1 ----------------
__global__ void prep_cat_kernel(const float* __restrict__ W1, const float* __restrict__ b1) {
    int idx = blockIdx.x * 256 + threadIdx.x;
    if (idx < FF * FF) {
        int i = idx >> 7, c = idx & 127;
        int k = c >> 4, j = c & 15;
        d_Wcat[idx] = W1[k * (FF * DD) + i * DD + j];
    }
    if (idx < FF) {
        int k = idx >> 4, j = idx & 15;
        d_bcat[idx] = b1[k * DD + j];
    }
}

// ---------------- block-diag single + fused stats (128 nodes/CTA) ----------------
__global__ void __launch_bounds__(256) bdiag1_kernel(const float* __restrict__ X,
                                                     const float* __restrict__ W,
                                                     const float* __restrict__ B,
                                                     float* __restrict__ C) {
    __shared__ float sW[8 * 257];
    __shared__ float sB[128];
    __shared__ float sSum[128], sSq[128];
    int tid = threadIdx.x;
    for (int i = tid; i < 2048; i += 256) sW[(i >> 8) * 257 + (i & 255)] = W[i];
    if (tid < 128) { sB[tid] = B[tid]; sSum[tid] = 0.f; sSq[tid] = 0.f; }
    __syncthreads();
    int k = tid & 7;
    const float* wk = sW + k * 257;
    float s[16], q[16];
#pragma unroll
    for (int j = 0; j < 16; j++) { s[j] = 0.f; q[j] = 0.f; }

    for (int it = 0; it < 4; it++) {
        int n = blockIdx.x * 128 + it * 32 + (tid >> 3);
        if (n >= NN) break;
        const float4* xp = (const float4*)(X + ((size_t)n << 7) + k * DD);
        float x[16];
#pragma unroll
        for (int i = 0; i < 4; i++) {
            float4 v = xp[i];
            x[4*i] = v.x; x[4*i+1] = v.y; x[4*i+2] = v.z; x[4*i+3] = v.w;
        }
        float o[16];
#pragma unroll
        for (int j = 0; j < 16; j++) o[j] = sB[k * 16 + j];
#pragma unroll
        for (int i = 0; i < 16; i++) {
            float xi = x[i];
#pragma unroll
            for (int j = 0; j < 16; j++) o[j] += xi * wk[i * 16 + j];
        }
        float4* cp = (float4*)(C + ((size_t)n << 7) + k * DD);
#pragma unroll
        for (int i = 0; i < 4; i++)
            cp[i] = make_float4(o[4*i], o[4*i+1], o[4*i+2], o[4*i+3]);
#pragma unroll
        for (int j = 0; j < 16; j++) { s[j] += o[j]; q[j] += o[j] * o[j]; }
    }
#pragma unroll
    for (int off = 16; off >= 8; off >>= 1) {
#pragma unroll
        for (int j = 0; j < 16; j++) {
            s[j] += __shfl_xor_sync(0xFFFFFFFFu, s[j], off);
            q[j] += __shfl_xor_sync(0xFFFFFFFFu, q[j], off);
        }
    }
    if ((tid & 31) < 8) {
#pragma unroll
        for (int j = 0; j < 16; j++) {
            atomicAdd(&sSum[k * 16 + j], s[j]);
            atomicAdd(&sSq[k * 16 + j], q[j]);
        }
    }
    __syncthreads();
    if (tid < 128) {
        atomicAdd(&d_bsum[tid], sSum[tid]);
        atomicAdd(&d_bsq[tid], sSq[tid]);
    }
}

// ---------------- block-diag double + fused stats (128 nodes/CTA) ----------------
__global__ void __launch_bounds__(256) bdiag2_kernel(const float* __restrict__ X,
                                                     const float* __restrict__ W1,
                                                     const float* __restrict__ B1,
                                                     const float* __restrict__ W2,
                                                     const float* __restrict__ B2,
                                                     float* __restrict__ C) {
    __shared__ float sW1[8 * 257];
    __shared__ float sW2[8 * 257];
    __shared__ float sB1[128];
    __shared__ float sB2[128];
    __shared__ float sSum[128], sSq[128];
    int tid = threadIdx.x;
    for (int i = tid; i < 2048; i += 256) {
        sW1[(i >> 8) * 257 + (i & 255)] = W1[i];
        sW2[(i >> 8) * 257 + (i & 255)] = W2[i];
    }
    if (tid < 128) { sB1[tid] = B1[tid]; sB2[tid] = B2[tid]; sSum[tid] = 0.f; sSq[tid] = 0.f; }
    __syncthreads();
    int k = tid & 7;
    const float* w1 = sW1 + k * 257;
    const float* w2 = sW2 + k * 257;
    float s[16], q[16];
#pragma unroll
    for (int j = 0; j < 16; j++) { s[j] = 0.f; q[j] = 0.f; }

    for (int it = 0; it < 4; it++) {
        int n = blockIdx.x * 128 + it * 32 + (tid >> 3);
        if (n >= NN) break;
        const float4* xp = (const float4*)(X + ((size_t)n << 7) + k * DD);
        float x[16];
#pragma unroll
        for (int i = 0; i < 4; i++) {
            float4 v = xp[i];
            x[4*i] = v.x; x[4*i+1] = v.y; x[4*i+2] = v.z; x[4*i+3] = v.w;
        }
        float t[16];
#pragma unroll
        for (int j = 0; j < 16; j++) t[j] = sB1[k * 16 + j];
#pragma unroll
        for (int i = 0; i < 16; i++) {
            float xi = x[i];
#pragma unroll
            for (int j = 0; j < 16; j++) t[j] += xi * w1[i * 16 + j];
        }
#pragma unroll
        for (int j = 0; j < 16; j++) t[j] = fmaxf(t[j], 0.f);
        float o[16];
#pragma unroll
        for (int j = 0; j < 16; j++) o[j] = sB2[k * 16 + j];
#pragma unroll
        for (int i = 0; i < 16; i++) {
            float ti = t[i];
#pragma unroll
            for (int j = 0; j < 16; j++) o[j] += ti * w2[i * 16 + j];
        }
        float4* cp = (float4*)(C + ((size_t)n << 7) + k * DD);
#pragma unroll
        for (int i = 0; i < 4; i++)
            cp[i] = make_float4(o[4*i], o[4*i+1], o[4*i+2], o[4*i+3]);
#pragma unroll
        for (int j = 0; j < 16; j++) { s[j] += o[j]; q[j] += o[j] * o[j]; }
    }
#pragma unroll
    for (int off = 16; off >= 8; off >>= 1) {
#pragma unroll
        for (int j = 0; j < 16; j++) {
            s[j] += __shfl_xor_sync(0xFFFFFFFFu, s[j], off);
            q[j] += __shfl_xor_sync(0xFFFFFFFFu, q[j], off);
        }
    }
    if ((tid & 31) < 8) {
#pragma unroll
        for (int j = 0; j < 16; j++) {
            atomicAdd(&sSum[k * 16 + j], s[j]);
            atomicAdd(&sSq[k * 16 + j], q[j]);
        }
    }
    __syncthreads();
    if (tid < 128) {
        atomicAdd(&d_bsum[tid], sSum[tid]);
        atomicAdd(&d_bsq[tid], sSq[tid]);
    }
}

// ---------------- pooling (applies final BN on the fly) ----------------
__global__ void zero_out_kernel(float* __restrict__ out) {
    int idx = blockIdx.x * 256 + threadIdx.x;
    if (idx < GG * FF) out[idx] = 0.f;
}
__global__ void __launch_bounds__(256) pool_kernel(const float* __restrict__ z,
                                                   const int* __restrict__ batch,
                                                   float* __restrict__ out) {
    int idx = blockIdx.x * 256 + threadIdx.x;
    if (idx >= NN * 32) return;
    int n = idx >> 5;
    int f4 = (idx & 31) << 2;
    int g = batch[n];
    float4 v = *(const float4*)(z + ((size_t)n << 7) + f4);
    float4 sc = *(const float4*)&d_scale[f4];
    float4 sh = *(const float4*)&d_shift[f4];
    v.x = v.x * sc.x + sh.x; v.y = v.y * sc.y + sh.y;
    v.z = v.z * sc.z + sh.z; v.w = v.w * sc.w + sh.w;
    float* op = out + (size_t)g * FF + f4;
    asm volatile("red.global.add.v4.f32 [%0], {%1,%2,%3,%4};"
                 :: "l"(op), "f"(v.x), "f"(v.y), "f"(v.z), "f"(v.w) : "memory");
}

// ---------------- host orchestration ----------------
extern "C" void kernel_launch(void* const* d_in, const int* in_sizes, int n_in,
                              void* d_out, int out_size) {
    const float* x     = (const float*)d_in[0];
    const int*   ei    = (const int*)d_in[1];
    const int*   batch = (const int*)d_in[2];
    const float* gc_W1 = (const float*)d_in[4];
    const float* gc_b1 = (const float*)d_in[5];
    const float* gc_W2 = (const float*)d_in[6];
    const float* gc_b2 = (const float*)d_in[7];
    const float* gc_g  = (const float*)d_in[8];
    const float* gc_be = (const float*)d_in[9];
    const float* h0_W1 = (const float*)d_in[10];
    const float* h0_b1 = (const float*)d_in[11];
    const float* h0_W2 = (const float*)d_in[12];
    const float* h0_b2 = (const float*)d_in[13];
    const float* h0_g  = (const float*)d_in[14];
    const float* h0_be = (const float*)d_in[15];
    const float* h1_W1 = (const float*)d_in[16];
    const float* h1_b1 = (const float*)d_in[17];
    const float* h1_W2 = (const float*)d_in[18];
    const float* h1_b2 = (const float*)d_in[19];
    const float* h1_g  = (const float*)d_in[20];
    const float* h1_be = (const float*)d_in[21];
    float* out = (float*)d_out;

    const int* src = ei;
    const int* dst = ei + EE;

    float *pagg, *pt, *pz, *pWcat, *pbcat;
    cudaGetSymbolAddress((void**)&pagg, d_agg);
    cudaGetSymbolAddress((void**)&pt, d_t);
    cudaGetSymbolAddress((void**)&pz, d_z);
    cudaGetSymbolAddress((void**)&pWcat, d_Wcat);
    cudaGetSymbolAddress((void**)&pbcat, d_bcat);

    cudaFuncSetAttribute(gemm_mma_kernel, cudaFuncAttributeMaxDynamicSharedMemorySize, SM_TOTAL);

    const int grid_nf   = (NN * 32 + 255) / 256;
    const int grid_cv   = (NN * 16 + 255) / 256;
    const int grid_e    = (EE + 255) / 256;
    const int grid_gemm = (NN + 127) / 128;
    const int grid_bd   = (NN + 127) / 128;

    // CSR build
    zero_deg_kernel<<<NB, 256>>>();
    hist_kernel<<<grid_e, 256>>>(dst);
    scan1_kernel<<<NB, 256>>>();
    scan2_kernel<<<1, 256>>>();
    scan3_kernel<<<NB, 256>>>();
    fill_kernel<<<grid_e, 256>>>(src, dst);

    // layer 0 input: x -> fp16 (identity), gather
    bnh_kernel<<<grid_cv, 256>>>(x, 0, 1);
    gather_kernel<<<grid_nf, 256>>>();

    for (int i = 0; i < GC; i++) {
        gemm_mma_kernel<<<grid_gemm, 256, SM_TOTAL>>>(pagg, gc_W1 + i * FF * FF, gc_b1 + i * FF, pt, NN, 1, 0);
        gemm_mma_kernel<<<grid_gemm, 256, SM_TOTAL>>>(pt,   gc_W2 + i * FF * FF, gc_b2 + i * FF, pz, NN, 0, 1);
        bn_fin_kernel<<<1, 128>>>(gc_g + i * FF, gc_be + i * FF);
        bnh_kernel<<<grid_cv, 256>>>(pz, (i < GC - 1) ? 1 : 0, 0);
        gather_kernel<<<grid_nf, 256>>>();
    }

    // head layer 0
    prep_cat_kernel<<<64, 256>>>(h0_W1, h0_b1);
    gemm_mma_kernel<<<grid_gemm, 256, SM_TOTAL>>>(pagg, pWcat, pbcat, pt, NN, 1, 0);
    bdiag1_kernel<<<grid_bd, 256>>>(pt, h0_W2, h0_b2, pz);
    bn_fin_kernel<<<1, 128>>>(h0_g, h0_be);
    bnh_kernel<<<grid_cv, 256>>>(pz, 1, 0);
    gather_kernel<<<grid_nf, 256>>>();

    // head layer 1
    bdiag2_kernel<<<grid_bd, 256>>>(pagg, h1_W1, h1_b1, h1_W2, h1_b2, pz);
    bn_fin_kernel<<<1, 128>>>(h1_g, h1_be);

    // pooling with final BN applied on the fly
    zero_out_kernel<<<(GG * FF + 255) / 256, 256>>>(out);
    pool_kernel<<<grid_nf, 256>>>(pz, batch, out);
}